// round 11
// baseline (speedup 1.0000x reference)
#include <cuda_runtime.h>
#include <cuda_bf16.h>
#include <cuda_fp8.h>
#include <stdint.h>
#include <math.h>

#define NMAX 10240
#define EMAX 340000
#define D 256
#define INMAX 512
#define TEMP_INV 2.0f
#define LAM 1e-3f
#define BN_EPS 1e-5f
#define FP8_SCALE 16.0f
// dot computed on (16 z) . (16 z) = 256 * true dot
#define NEG_EXP_SCALE (TEMP_INV / 256.0f)

// ------------------------------ scratch ------------------------------
__device__ __align__(16) float g_t[NMAX * D];
__device__ __align__(16) float g_h[NMAX * D];
__device__ __align__(16) float g_p[NMAX * D];
__device__ __align__(16) __nv_bfloat16 g_featb[NMAX * INMAX];
__device__ __align__(16) __nv_bfloat16 g_xwb[NMAX * D];
__device__ __align__(16) __nv_bfloat16 g_h1b[NMAX * D];
__device__ __align__(16) __nv_bfloat16 g_tb[NMAX * D];
__device__ __align__(16) __nv_bfloat16 g_transb[NMAX * D];
__device__ __align__(16) __nv_bfloat16 g_zh[NMAX * D];
__device__ __align__(16) __nv_bfloat16 g_qh[NMAX * D];
__device__ __align__(16) uint8_t g_ze[NMAX * D];   // e4m3, scaled x16
__device__ __align__(16) uint8_t g_qe[NMAX * D];   // e4m3, scaled x16
__device__ __align__(16) __nv_bfloat16 g_W1b[INMAX * D];
__device__ __align__(16) __nv_bfloat16 g_W2b[D * D];
__device__ __align__(16) __nv_bfloat16 g_Wt1b[INMAX * D];
__device__ __align__(16) __nv_bfloat16 g_Wt2b[D * D];
__device__ __align__(16) __nv_bfloat16 g_Wpb[D * D];
__device__ float g_degout[NMAX];
__device__ float g_degin[NMAX];
__device__ float g_rsd[NMAX];
__device__ int   g_cnt[NMAX];
__device__ int   g_off[NMAX + 1];
__device__ int   g_cur[NMAX];
__device__ int   g_csrc[EMAX];
__device__ float g_musum[D];
__device__ float g_varsum[D];
__device__ float g_s1[NMAX];
__device__ float g_s2[NMAX];
__device__ float g_pos[NMAX];

// ------------------------------ small kernels ------------------------------
__global__ void zero2_k(float* a, float* b, int n) {
    int i = blockIdx.x * blockDim.x + threadIdx.x;
    if (i < n) { a[i] = 0.f; b[i] = 0.f; }
}
__global__ void zero3_k(float* a, float* b, int* c, int n) {
    int i = blockIdx.x * blockDim.x + threadIdx.x;
    if (i < n) { a[i] = 0.f; b[i] = 0.f; c[i] = 0; }
}
__global__ void zero_k(float* p, int n) {
    int i = blockIdx.x * blockDim.x + threadIdx.x;
    if (i < n) p[i] = 0.f;
}

__global__ void f2b_k(const float* __restrict__ x, __nv_bfloat16* __restrict__ y,
                      int n, int ntot) {
    int i = blockIdx.x * blockDim.x + threadIdx.x;
    if (i < ntot) y[i] = __float2bfloat16(i < n ? x[i] : 0.f);
}

__global__ void wconvall_k(const float* W1, const float* Wt1,
                           const float* W2, const float* Wt2, const float* Wp,
                           __nv_bfloat16* W1b, __nv_bfloat16* Wt1b,
                           __nv_bfloat16* W2b, __nv_bfloat16* Wt2b,
                           __nv_bfloat16* Wpb) {
    int i = blockIdx.x * blockDim.x + threadIdx.x;
    const float* W; __nv_bfloat16* O; int K, li;
    if (i < 131072)        { W = W1;  O = W1b;  K = 512; li = i; }
    else if (i < 262144)   { W = Wt1; O = Wt1b; K = 512; li = i - 131072; }
    else if (i < 327680)   { W = W2;  O = W2b;  K = 256; li = i - 262144; }
    else if (i < 393216)   { W = Wt2; O = Wt2b; K = 256; li = i - 327680; }
    else if (i < 458752)   { W = Wp;  O = Wpb;  K = 256; li = i - 393216; }
    else return;
    int k = li >> 8, n = li & 255;
    O[n * K + k] = __float2bfloat16(W[(size_t)k * 256 + n]);
}

__global__ void zerohtail_k(__nv_bfloat16* p, int from, int to) {
    int i = from + blockIdx.x * blockDim.x + threadIdx.x;
    if (i < to) p[i] = __float2bfloat16(0.f);
}

__global__ void degree_k(const int* __restrict__ src, const int* __restrict__ dst,
                         float* dout, float* din, int* cnt, int e) {
    int i = blockIdx.x * blockDim.x + threadIdx.x;
    if (i < e) {
        atomicAdd(&dout[src[i]], 1.f);
        atomicAdd(&din[dst[i]], 1.f);
        atomicAdd(&cnt[dst[i]], 1);
    }
}

__global__ void rsdcur_k(const float* __restrict__ dout, float* rsd, int* cur, int n) {
    int i = blockIdx.x * blockDim.x + threadIdx.x;
    if (i < n) { rsd[i] = rsqrtf(dout[i]); cur[i] = 0; }
}

__global__ void scan_k(const int* __restrict__ cnt, int* off, int n) {
    __shared__ int ts[1024];
    int t = threadIdx.x;
    int L = (n + 1023) >> 10;
    int b = t * L, eidx = min(b + L, n);
    int s = 0;
    for (int i = b; i < eidx; i++) s += cnt[i];
    ts[t] = s;
    __syncthreads();
    for (int d2 = 1; d2 < 1024; d2 <<= 1) {
        int v = (t >= d2) ? ts[t - d2] : 0;
        __syncthreads();
        ts[t] += v;
        __syncthreads();
    }
    int base = (t == 0) ? 0 : ts[t - 1];
    for (int i = b; i < eidx; i++) { off[i] = base; base += cnt[i]; }
    if (t == 1023) off[n] = ts[1023];
}

__global__ void fillcsr_k(const int* __restrict__ src, const int* __restrict__ dst,
                          const int* __restrict__ off, int* cur, int* csrc, int e) {
    int i = blockIdx.x * blockDim.x + threadIdx.x;
    if (i < e) {
        int d = dst[i];
        int p = off[d] + atomicAdd(&cur[d], 1);
        csrc[p] = src[i];
    }
}

__global__ void gather_agg_k(const __nv_bfloat16* __restrict__ xw,
                             const int* __restrict__ csrc, const int* __restrict__ off,
                             const float* __restrict__ rsd, const float* __restrict__ din,
                             const float* __restrict__ bias,
                             float* outf, __nv_bfloat16* outh, int n, int relu) {
    int d = (blockIdx.x * blockDim.x + threadIdx.x) >> 5;
    int lane = threadIdx.x & 31;
    if (d >= n) return;
    float acc[8] = {};
    int p0 = off[d], p1 = off[d + 1];
    int p = p0;
    for (; p + 4 <= p1; p += 4) {
        int s0 = __ldg(csrc + p), s1i = __ldg(csrc + p + 1);
        int s2i = __ldg(csrc + p + 2), s3i = __ldg(csrc + p + 3);
        float w0 = rsd[s0], w1 = rsd[s1i], w2 = rsd[s2i], w3 = rsd[s3i];
        uint4 v0 = *((const uint4*)(xw + (size_t)s0 * D) + lane);
        uint4 v1 = *((const uint4*)(xw + (size_t)s1i * D) + lane);
        uint4 v2 = *((const uint4*)(xw + (size_t)s2i * D) + lane);
        uint4 v3 = *((const uint4*)(xw + (size_t)s3i * D) + lane);
        const __nv_bfloat16* h0 = (const __nv_bfloat16*)&v0;
        const __nv_bfloat16* h1 = (const __nv_bfloat16*)&v1;
        const __nv_bfloat16* h2 = (const __nv_bfloat16*)&v2;
        const __nv_bfloat16* h3 = (const __nv_bfloat16*)&v3;
#pragma unroll
        for (int k = 0; k < 8; k++)
            acc[k] += __bfloat162float(h0[k]) * w0 + __bfloat162float(h1[k]) * w1 +
                      __bfloat162float(h2[k]) * w2 + __bfloat162float(h3[k]) * w3;
    }
    for (; p < p1; p++) {
        int s = __ldg(csrc + p);
        float w = rsd[s];
        uint4 v = *((const uint4*)(xw + (size_t)s * D) + lane);
        const __nv_bfloat16* hv = (const __nv_bfloat16*)&v;
#pragma unroll
        for (int k = 0; k < 8; k++) acc[k] += __bfloat162float(hv[k]) * w;
    }
    float sc = rsqrtf(din[d]);
    int col = lane * 8;
    float o[8];
#pragma unroll
    for (int k = 0; k < 8; k++) {
        float v = acc[k] * sc + bias[col + k];
        o[k] = relu ? fmaxf(v, 0.f) : v;
    }
    if (outf) {
        float4* fr = (float4*)(outf + (size_t)d * D + col);
        fr[0] = make_float4(o[0], o[1], o[2], o[3]);
        fr[1] = make_float4(o[4], o[5], o[6], o[7]);
    }
    if (outh) {
        __nv_bfloat16 hb[8];
#pragma unroll
        for (int k = 0; k < 8; k++) hb[k] = __float2bfloat16(o[k]);
        *(uint4*)(outh + (size_t)d * D + col) = *(uint4*)hb;
    }
}

__global__ void bnstat_k(const float* __restrict__ t, float* musum, float* varsum, int M) {
    int col = threadIdx.x;
    int rpb = (M + gridDim.x - 1) / gridDim.x;
    int r0 = blockIdx.x * rpb;
    int r1 = min(r0 + rpb, M);
    float s = 0.f, s2 = 0.f;
    for (int r = r0; r < r1; r++) {
        float v = t[(size_t)r * D + col];
        s += v; s2 += v * v;
    }
    atomicAdd(&musum[col], s);
    atomicAdd(&varsum[col], s2);
}

__global__ void bnapply_k(const float* __restrict__ t, const float* __restrict__ musum,
                          const float* __restrict__ varsum,
                          const float* __restrict__ gamma, const float* __restrict__ beta,
                          __nv_bfloat16* th, int M) {
    int i = blockIdx.x * blockDim.x + threadIdx.x;
    if (i < M * D) {
        int c = i & (D - 1);
        float mu = musum[c] / M;
        float var = varsum[c] / M - mu * mu;
        float v = (t[i] - mu) * rsqrtf(var + BN_EPS) * gamma[c] + beta[c];
        th[i] = __float2bfloat16(fmaxf(v, 0.f));
    }
}

// normalize both h->zh/ze and p->qh/qe (bf16 + scaled e4m3), blockIdx.y selects
__global__ void norml2_k(const float* __restrict__ x0, __nv_bfloat16* __restrict__ zh0,
                         uint8_t* __restrict__ ze0,
                         const float* __restrict__ x1, __nv_bfloat16* __restrict__ zh1,
                         uint8_t* __restrict__ ze1, int M, int Mpad) {
    const float* x = blockIdx.y ? x1 : x0;
    __nv_bfloat16* zh = blockIdx.y ? zh1 : zh0;
    uint8_t* ze = blockIdx.y ? ze1 : ze0;
    int row = (blockIdx.x * blockDim.x + threadIdx.x) >> 5;
    int lane = threadIdx.x & 31;
    if (row >= Mpad) return;
    __nv_bfloat16* hr = zh + (size_t)row * D;
    uint8_t* er = ze + (size_t)row * D;
    if (row >= M) {
#pragma unroll
        for (int c = 0; c < D / 32; c++) {
            hr[lane + 32 * c] = __float2bfloat16(0.f);
            er[lane + 32 * c] = 0;
        }
        return;
    }
    const float* xr = x + (size_t)row * D;
    float s = 0.f;
#pragma unroll
    for (int c = 0; c < D / 32; c++) {
        float v = xr[lane + 32 * c];
        s += v * v;
    }
#pragma unroll
    for (int o = 16; o > 0; o >>= 1) s += __shfl_xor_sync(0xffffffffu, s, o);
    float inv = 1.f / fmaxf(sqrtf(s), 1e-12f);
#pragma unroll
    for (int c = 0; c < D / 32; c++) {
        int f = lane + 32 * c;
        float v = xr[f] * inv;
        hr[f] = __float2bfloat16(v);
        er[f] = (uint8_t)__nv_cvt_float_to_fp8(v * FP8_SCALE, __NV_SATFINITE, __NV_E4M3);
    }
}

__global__ void gather_pos_k(const __nv_bfloat16* __restrict__ zh,
                             const __nv_bfloat16* __restrict__ qh,
                             const int* __restrict__ csrc, const int* __restrict__ off,
                             float* pos, int n) {
    int d = (blockIdx.x * blockDim.x + threadIdx.x) >> 5;
    int lane = threadIdx.x & 31;
    if (d >= n) return;
    uint4 qv = *((const uint4*)(qh + (size_t)d * D) + lane);
    const __nv_bfloat16* qe = (const __nv_bfloat16*)&qv;
    float qf[8];
#pragma unroll
    for (int k = 0; k < 8; k++) qf[k] = __bfloat162float(qe[k]);
    float sz[8] = {};
    int p0 = off[d], p1 = off[d + 1];
    int p = p0;
    for (; p + 4 <= p1; p += 4) {
        int s0 = __ldg(csrc + p), s1i = __ldg(csrc + p + 1);
        int s2i = __ldg(csrc + p + 2), s3i = __ldg(csrc + p + 3);
        uint4 v0 = *((const uint4*)(zh + (size_t)s0 * D) + lane);
        uint4 v1 = *((const uint4*)(zh + (size_t)s1i * D) + lane);
        uint4 v2 = *((const uint4*)(zh + (size_t)s2i * D) + lane);
        uint4 v3 = *((const uint4*)(zh + (size_t)s3i * D) + lane);
        const __nv_bfloat16* h0 = (const __nv_bfloat16*)&v0;
        const __nv_bfloat16* h1 = (const __nv_bfloat16*)&v1;
        const __nv_bfloat16* h2 = (const __nv_bfloat16*)&v2;
        const __nv_bfloat16* h3 = (const __nv_bfloat16*)&v3;
#pragma unroll
        for (int k = 0; k < 8; k++)
            sz[k] += __bfloat162float(h0[k]) + __bfloat162float(h1[k]) +
                     __bfloat162float(h2[k]) + __bfloat162float(h3[k]);
    }
    for (; p < p1; p++) {
        int s = __ldg(csrc + p);
        uint4 v = *((const uint4*)(zh + (size_t)s * D) + lane);
        const __nv_bfloat16* hv = (const __nv_bfloat16*)&v;
#pragma unroll
        for (int k = 0; k < 8; k++) sz[k] += __bfloat162float(hv[k]);
    }
    float dot = 0.f;
#pragma unroll
    for (int k = 0; k < 8; k++) dot += sz[k] * qf[k];
#pragma unroll
    for (int o = 16; o > 0; o >>= 1) dot += __shfl_xor_sync(0xffffffffu, dot, o);
    if (lane == 0) pos[d] = dot * TEMP_INV;
}

__global__ void mneg_loss_k(const float* __restrict__ s1, const float* __restrict__ s2,
                            const float* __restrict__ pos,
                            const int* __restrict__ csrc, const int* __restrict__ off,
                            float* out, int n) {
    __shared__ float ws[8];
    int tid = threadIdx.x;
    int lane = tid & 31, warp = tid >> 5;
    int d = (blockIdx.x * blockDim.x + tid) >> 5;
    float contrib = 0.f;
    if (d < n) {
        float base = s1[d];
        float acc = 0.f;
        int p0 = off[d], p1 = off[d + 1];
        for (int p = p0 + lane; p < p1; p += 32)
            acc += __logf(base + LAM * s2[__ldg(csrc + p)]);
#pragma unroll
        for (int o = 16; o > 0; o >>= 1) acc += __shfl_xor_sync(0xffffffffu, acc, o);
        if (lane == 0) contrib = (acc - pos[d]) / (float)(p1 - p0);
    }
    if (lane == 0) ws[warp] = contrib;
    __syncthreads();
    if (tid == 0) {
        float t = 0.f;
#pragma unroll
        for (int w = 0; w < 8; w++) t += ws[w];
        atomicAdd(out, t / n);
    }
}

// ---------------- mma helpers ----------------
__device__ __forceinline__ void ldsm4(uint32_t addr, uint32_t& r0, uint32_t& r1,
                                      uint32_t& r2, uint32_t& r3) {
    asm volatile("ldmatrix.sync.aligned.m8n8.x4.shared.b16 {%0,%1,%2,%3}, [%4];"
                 : "=r"(r0), "=r"(r1), "=r"(r2), "=r"(r3) : "r"(addr));
}
__device__ __forceinline__ void mma16816(float* c, const uint32_t* a,
                                         uint32_t b0, uint32_t b1) {
    asm volatile(
        "mma.sync.aligned.m16n8k16.row.col.f32.bf16.bf16.f32 "
        "{%0,%1,%2,%3}, {%4,%5,%6,%7}, {%8,%9}, {%0,%1,%2,%3};"
        : "+f"(c[0]), "+f"(c[1]), "+f"(c[2]), "+f"(c[3])
        : "r"(a[0]), "r"(a[1]), "r"(a[2]), "r"(a[3]), "r"(b0), "r"(b1));
}
__device__ __forceinline__ void mma16832fp8(float* c, const uint32_t* a,
                                            uint32_t b0, uint32_t b1) {
    asm volatile(
        "mma.sync.aligned.m16n8k32.row.col.f32.e4m3.e4m3.f32 "
        "{%0,%1,%2,%3}, {%4,%5,%6,%7}, {%8,%9}, {%0,%1,%2,%3};"
        : "+f"(c[0]), "+f"(c[1]), "+f"(c[2]), "+f"(c[3])
        : "r"(a[0]), "r"(a[1]), "r"(a[2]), "r"(a[3]), "r"(b0), "r"(b1));
}
__device__ __forceinline__ void cp16(uint32_t saddr, const void* g) {
    asm volatile("cp.async.cg.shared.global [%0], [%1], 16;"
                 :: "r"(saddr), "l"(g) : "memory");
}
__device__ __forceinline__ void loadB64(uint32_t sdst, const __nv_bfloat16* Bg,
                                        int k0, int ldb, int tid) {
#pragma unroll
    for (int t = 0; t < 4; t++) {
        int c = tid + t * 256;
        int row = c >> 3, ch = c & 7;
        uint32_t off = (uint32_t)(row * 128 + ((ch ^ (row & 7)) << 4));
        cp16(sdst + off, Bg + (size_t)row * ldb + k0 + ch * 8);
    }
    asm volatile("cp.async.commit_group;" ::: "memory");
}

#define STAGE_BYTES 32768

// ---------------- bf16 tensor GEMM (pipelined): C = A[Mpad,K] @ Wt[256,K]^T ----------------
__global__ __launch_bounds__(256, 2) void gemm_bf16_k(
    const __nv_bfloat16* __restrict__ A, const __nv_bfloat16* __restrict__ Wt,
    const float* __restrict__ bias, float* __restrict__ Cf,
    __nv_bfloat16* __restrict__ Ch, int M, int K, int relu) {
    extern __shared__ char dsm[];
    uint32_t sbase = (uint32_t)__cvta_generic_to_shared(dsm);
    int tid = threadIdx.x;
    int lane = tid & 31, warp = tid >> 5;
    int wi = warp >> 1, wj = warp & 1;
    int i0 = blockIdx.x * 128, j0 = blockIdx.y * 128;

    int a_row = (lane & 15);
    int a_chsel = (lane >> 4);
    int b_row = (lane & 7) + ((lane >> 4) & 1) * 8;
    int b_chsel = ((lane >> 3) & 1);

    const __nv_bfloat16* Ag = A + (size_t)i0 * K;
    const __nv_bfloat16* Bg = Wt + (size_t)j0 * K;

    float acc[2][8][4];
#pragma unroll
    for (int x = 0; x < 2; x++)
#pragma unroll
        for (int y = 0; y < 8; y++)
#pragma unroll
            for (int v = 0; v < 4; v++) acc[x][y][v] = 0.f;

    int KT = K >> 6;
    loadB64(sbase, Ag, 0, K, tid);
    loadB64(sbase + 16384, Bg, 0, K, tid);
    for (int kt = 0; kt < KT; kt++) {
        asm volatile("cp.async.wait_group 0;" ::: "memory");
        __syncthreads();
        if (kt + 1 < KT) {
            uint32_t sa = sbase + ((kt + 1) & 1) * STAGE_BYTES;
            loadB64(sa, Ag, (kt + 1) * 64, K, tid);
            loadB64(sa + 16384, Bg, (kt + 1) * 64, K, tid);
        }
        uint32_t sAu = sbase + (kt & 1) * STAGE_BYTES;
        uint32_t sBu = sAu + 16384;
#pragma unroll
        for (int ks = 0; ks < 4; ks++) {
            uint32_t afr[2][4];
#pragma unroll
            for (int mt = 0; mt < 2; mt++) {
                int row = wi * 32 + mt * 16 + a_row;
                int ch = ks * 2 + a_chsel;
                uint32_t addr = sAu + (uint32_t)(row * 128 + ((ch ^ (row & 7)) << 4));
                ldsm4(addr, afr[mt][0], afr[mt][1], afr[mt][2], afr[mt][3]);
            }
#pragma unroll
            for (int p = 0; p < 4; p++) {
                int nrow = wj * 64 + p * 16 + b_row;
                int ch = ks * 2 + b_chsel;
                uint32_t addr = sBu + (uint32_t)(nrow * 128 + ((ch ^ (nrow & 7)) << 4));
                uint32_t bf0, bf1, bf2, bf3;
                ldsm4(addr, bf0, bf1, bf2, bf3);
#pragma unroll
                for (int mt = 0; mt < 2; mt++) {
                    mma16816(acc[mt][2 * p], afr[mt], bf0, bf1);
                    mma16816(acc[mt][2 * p + 1], afr[mt], bf2, bf3);
                }
            }
        }
        __syncthreads();
    }
#pragma unroll
    for (int mt = 0; mt < 2; mt++) {
        int r0 = i0 + wi * 32 + mt * 16 + (lane >> 2);
#pragma unroll
        for (int nt = 0; nt < 8; nt++) {
            int col = j0 + wj * 64 + nt * 8 + (lane & 3) * 2;
            float b0 = bias ? bias[col] : 0.f;
            float b1 = bias ? bias[col + 1] : 0.f;
            float v0 = acc[mt][nt][0] + b0, v1 = acc[mt][nt][1] + b1;
            float v2 = acc[mt][nt][2] + b0, v3 = acc[mt][nt][3] + b1;
            if (relu) {
                v0 = fmaxf(v0, 0.f); v1 = fmaxf(v1, 0.f);
                v2 = fmaxf(v2, 0.f); v3 = fmaxf(v3, 0.f);
            }
            if (r0 < M) {
                if (Cf) { Cf[(size_t)r0 * D + col] = v0; Cf[(size_t)r0 * D + col + 1] = v1; }
                if (Ch) {
                    Ch[(size_t)r0 * D + col] = __float2bfloat16(v0);
                    Ch[(size_t)r0 * D + col + 1] = __float2bfloat16(v1);
                }
            }
            int r1 = r0 + 8;
            if (r1 < M) {
                if (Cf) { Cf[(size_t)r1 * D + col] = v2; Cf[(size_t)r1 * D + col + 1] = v3; }
                if (Ch) {
                    Ch[(size_t)r1 * D + col] = __float2bfloat16(v2);
                    Ch[(size_t)r1 * D + col + 1] = __float2bfloat16(v3);
                }
            }
        }
    }
}

// ---------------- FP8 fused dual negsum ----------------
// s1[i] += sum_j exp(2 z_i.z_j), s2[i] += sum_j exp(2 z_i.q_j); inputs e4m3 x16.
// Tile 128x128, K=256 fp8 = 2 smem k-halves (128 rows x 128B) x 4 k32 steps each.
// A resident (32KB); B tiles double-buffered (2 x 32KB).
__device__ __forceinline__ void load_tile_fp8(uint32_t sdst, const uint8_t* G, int tid) {
#pragma unroll
    for (int t = 0; t < 8; t++) {
        int c = tid + t * 256;                 // 0..2047 16B chunks
        int blk = c >> 10, idx = c & 1023;     // blk = k-half
        int row = idx >> 3, ch = idx & 7;
        uint32_t off = (uint32_t)(blk * 16384 + row * 128 + ((ch ^ (row & 7)) << 4));
        cp16(sdst + off, G + (size_t)row * 256 + blk * 128 + ch * 16);
    }
    asm volatile("cp.async.commit_group;" ::: "memory");
}

__global__ __launch_bounds__(256, 2) void negfp8_k(
    const uint8_t* __restrict__ Z8, const uint8_t* __restrict__ Q8,
    float* __restrict__ s1, float* __restrict__ s2, int n, int nJT) {
    extern __shared__ char dsm[];
    uint32_t aBase = (uint32_t)__cvta_generic_to_shared(dsm);  // 32 KB
    uint32_t bBase = aBase + 32768;                             // 2 x 32 KB
    int tid = threadIdx.x;
    int lane = tid & 31, warp = tid >> 5;
    int wi = warp >> 1, wj = warp & 1;
    int i0 = blockIdx.x * 128;

    int a_row = (lane & 15);
    int a_chsel = (lane >> 4);
    int b_row = (lane & 7) + ((lane >> 4) & 1) * 8;
    int b_chsel = ((lane >> 3) & 1);

    int gy = gridDim.y;
    int cnt = (nJT - (int)blockIdx.y + gy - 1) / gy;
    int T = 2 * cnt;

    load_tile_fp8(aBase, Z8 + (size_t)i0 * 256, tid);
    load_tile_fp8(bBase, Z8 + (size_t)((int)blockIdx.y * 128) * 256, tid);

    float rs[2][2][2];
#pragma unroll
    for (int a = 0; a < 2; a++)
#pragma unroll
        for (int b = 0; b < 2; b++)
#pragma unroll
            for (int c = 0; c < 2; c++) rs[a][b][c] = 0.f;

    for (int k = 0; k < T; k++) {
        asm volatile("cp.async.wait_group 0;" ::: "memory");
        __syncthreads();   // B(k) visible to all warps before compute and next prefetch
        if (k + 1 < T) {
            int nk = k + 1;
            int njt = (int)blockIdx.y + (nk >> 1) * gy;
            const uint8_t* G = ((nk & 1) ? Q8 : Z8) + (size_t)(njt * 128) * 256;
            load_tile_fp8(bBase + (uint32_t)((nk & 1) * 32768), G, tid);
        }
        uint32_t bCur = bBase + (uint32_t)((k & 1) * 32768);
        float acc[2][8][4];
#pragma unroll
        for (int x = 0; x < 2; x++)
#pragma unroll
            for (int y = 0; y < 8; y++)
#pragma unroll
                for (int v = 0; v < 4; v++) acc[x][y][v] = 0.f;
#pragma unroll
        for (int blk = 0; blk < 2; blk++) {
            uint32_t sAu = aBase + (uint32_t)(blk * 16384);
            uint32_t sBu = bCur + (uint32_t)(blk * 16384);
#pragma unroll
            for (int ks = 0; ks < 4; ks++) {
                uint32_t afr[2][4];
#pragma unroll
                for (int mt = 0; mt < 2; mt++) {
                    int row = wi * 32 + mt * 16 + a_row;
                    int ch = ks * 2 + a_chsel;
                    uint32_t addr = sAu + (uint32_t)(row * 128 + ((ch ^ (row & 7)) << 4));
                    ldsm4(addr, afr[mt][0], afr[mt][1], afr[mt][2], afr[mt][3]);
                }
#pragma unroll
                for (int p = 0; p < 4; p++) {
                    int nrow = wj * 64 + p * 16 + b_row;
                    int ch = ks * 2 + b_chsel;
                    uint32_t addr = sBu + (uint32_t)(nrow * 128 + ((ch ^ (nrow & 7)) << 4));
                    uint32_t bf0, bf1, bf2, bf3;
                    ldsm4(addr, bf0, bf1, bf2, bf3);
#pragma unroll
                    for (int mt = 0; mt < 2; mt++) {
                        mma16832fp8(acc[mt][2 * p], afr[mt], bf0, bf1);
                        mma16832fp8(acc[mt][2 * p + 1], afr[mt], bf2, bf3);
                    }
                }
            }
        }
        // epilogue: exp + masked rowsum
        int sel = k & 1;
        int j0 = ((int)blockIdx.y + (k >> 1) * gy) * 128;
#pragma unroll
        for (int mt = 0; mt < 2; mt++) {
#pragma unroll
            for (int nt = 0; nt < 8; nt++) {
                int j = j0 + wj * 64 + nt * 8 + (lane & 3) * 2;
                float e0 = (j < n) ? __expf(acc[mt][nt][0] * NEG_EXP_SCALE) : 0.f;
                float e1 = (j + 1 < n) ? __expf(acc[mt][nt][1] * NEG_EXP_SCALE) : 0.f;
                float e2 = (j < n) ? __expf(acc[mt][nt][2] * NEG_EXP_SCALE) : 0.f;
                float e3 = (j + 1 < n) ? __expf(acc[mt][nt][3] * NEG_EXP_SCALE) : 0.f;
                rs[sel][mt][0] += e0 + e1;
                rs[sel][mt][1] += e2 + e3;
            }
        }
        __syncthreads();   // all warps done reading buf(k) before refill at k+2
    }
#pragma unroll
    for (int sel = 0; sel < 2; sel++) {
        float* out = sel ? s2 : s1;
#pragma unroll
        for (int mt = 0; mt < 2; mt++) {
#pragma unroll
            for (int h = 0; h < 2; h++) {
                float v = rs[sel][mt][h];
                v += __shfl_xor_sync(0xffffffffu, v, 1);
                v += __shfl_xor_sync(0xffffffffu, v, 2);
                if ((lane & 3) == 0) {
                    int i = i0 + wi * 32 + mt * 16 + h * 8 + (lane >> 2);
                    if (i < n) atomicAdd(&out[i], v);
                }
            }
        }
    }
}

// ------------------------------ launcher ------------------------------
static float* symf(const void* s) { void* p = nullptr; cudaGetSymbolAddress(&p, s); return (float*)p; }
static int* symi(const void* s) { void* p = nullptr; cudaGetSymbolAddress(&p, s); return (int*)p; }
static __nv_bfloat16* symh(const void* s) { void* p = nullptr; cudaGetSymbolAddress(&p, s); return (__nv_bfloat16*)p; }
static uint8_t* symb(const void* s) { void* p = nullptr; cudaGetSymbolAddress(&p, s); return (uint8_t*)p; }

extern "C" void kernel_launch(void* const* d_in, const int* in_sizes, int n_in,
                              void* d_out, int out_size) {
    const float* feat  = (const float*)d_in[0];
    const float* W1    = (const float*)d_in[1];
    const float* b1    = (const float*)d_in[2];
    const float* W2    = (const float*)d_in[3];
    const float* b2    = (const float*)d_in[4];
    const float* Wt1   = (const float*)d_in[5];
    const float* bt1   = (const float*)d_in[6];
    const float* gamma = (const float*)d_in[7];
    const float* beta  = (const float*)d_in[8];
    const float* Wt2   = (const float*)d_in[9];
    const float* bt2   = (const float*)d_in[10];
    const float* Wp    = (const float*)d_in[11];
    const float* bp    = (const float*)d_in[12];
    const int*   src   = (const int*)d_in[13];
    const int*   dst   = (const int*)d_in[14];

    const int IN = 512;
    int n = in_sizes[0] / IN;
    int e = in_sizes[13];
    int nTI = (n + 127) / 128;
    int npad = nTI * 128;

    float* tbuf = symf(g_t);
    float* hbuf = symf(g_h);
    float* pbuf = symf(g_p);
    __nv_bfloat16* featb = symh(g_featb);
    __nv_bfloat16* xwb = symh(g_xwb);
    __nv_bfloat16* h1b = symh(g_h1b);
    __nv_bfloat16* tb = symh(g_tb);
    __nv_bfloat16* transb = symh(g_transb);
    __nv_bfloat16* zh = symh(g_zh);
    __nv_bfloat16* qh = symh(g_qh);
    uint8_t* ze = symb(g_ze);
    uint8_t* qe = symb(g_qe);
    __nv_bfloat16* W1b = symh(g_W1b);
    __nv_bfloat16* W2b = symh(g_W2b);
    __nv_bfloat16* Wt1b = symh(g_Wt1b);
    __nv_bfloat16* Wt2b = symh(g_Wt2b);
    __nv_bfloat16* Wpb = symh(g_Wpb);
    float* dout = symf(g_degout);
    float* din  = symf(g_degin);
    float* rsd  = symf(g_rsd);
    int* cnt = symi(g_cnt);
    int* off = symi(g_off);
    int* cur = symi(g_cur);
    int* csrc = symi(g_csrc);
    float* musum = symf(g_musum);
    float* varsum = symf(g_varsum);
    float* s1 = symf(g_s1);
    float* s2 = symf(g_s2);
    float* pos = symf(g_pos);
    float* out = (float*)d_out;

    int nd = n * D;
    int ndpad = npad * D;
    int tail = ndpad - nd;
    dim3 gemm_grid(nTI, 2);
    int node_warp_blocks = (n * 32 + 255) / 256;

    static cudaStream_t sA = nullptr, sB = nullptr;
    static cudaEvent_t evStart, evRoot, evCSR, evGCN, evNorm, evPos;
    if (sA == nullptr) {
        cudaStreamCreateWithFlags(&sA, cudaStreamNonBlocking);
        cudaStreamCreateWithFlags(&sB, cudaStreamNonBlocking);
        cudaEventCreateWithFlags(&evStart, cudaEventDisableTiming);
        cudaEventCreateWithFlags(&evRoot, cudaEventDisableTiming);
        cudaEventCreateWithFlags(&evCSR, cudaEventDisableTiming);
        cudaEventCreateWithFlags(&evGCN, cudaEventDisableTiming);
        cudaEventCreateWithFlags(&evNorm, cudaEventDisableTiming);
        cudaEventCreateWithFlags(&evPos, cudaEventDisableTiming);
        cudaFuncSetAttribute(gemm_bf16_k, cudaFuncAttributeMaxDynamicSharedMemorySize, 2 * STAGE_BYTES);
        cudaFuncSetAttribute(negfp8_k, cudaFuncAttributeMaxDynamicSharedMemorySize, 98304);
    }

    // ---- fork CSR chain to sB ----
    cudaEventRecord(evStart, 0);
    cudaStreamWaitEvent(sB, evStart, 0);
    zero3_k<<<(n + 255) / 256, 256, 0, sB>>>(dout, din, cnt, n);
    degree_k<<<(e + 255) / 256, 256, 0, sB>>>(src, dst, dout, din, cnt, e);
    rsdcur_k<<<(n + 255) / 256, 256, 0, sB>>>(dout, rsd, cur, n);
    scan_k<<<1, 1024, 0, sB>>>(cnt, off, n);
    fillcsr_k<<<(e + 255) / 256, 256, 0, sB>>>(src, dst, off, cur, csrc, e);
    cudaEventRecord(evCSR, sB);

    // ---- main: conversions ----
    f2b_k<<<(npad * IN + 255) / 256, 256>>>(feat, featb, n * IN, npad * IN);
    wconvall_k<<<(458752 + 255) / 256, 256>>>(W1, Wt1, W2, Wt2, Wp,
                                              W1b, Wt1b, W2b, Wt2b, Wpb);
    cudaEventRecord(evRoot, 0);

    // ---- fork GCN branch to sA ----
    cudaStreamWaitEvent(sA, evRoot, 0);
    gemm_bf16_k<<<gemm_grid, 256, 2 * STAGE_BYTES, sA>>>(featb, W1b, nullptr, nullptr, xwb, n, IN, 0);
    cudaStreamWaitEvent(sA, evCSR, 0);
    gather_agg_k<<<node_warp_blocks, 256, 0, sA>>>(xwb, csrc, off, rsd, din, b1, nullptr, h1b, n, 1);
    zerohtail_k<<<(tail + 255) / 256, 256, 0, sA>>>(h1b, nd, ndpad);
    gemm_bf16_k<<<gemm_grid, 256, 2 * STAGE_BYTES, sA>>>(h1b, W2b, nullptr, nullptr, xwb, n, D, 0);
    gather_agg_k<<<node_warp_blocks, 256, 0, sA>>>(xwb, csrc, off, rsd, din, b2, hbuf, nullptr, n, 0);
    cudaEventRecord(evGCN, sA);

    // ---- main: target MLP branch ----
    gemm_bf16_k<<<gemm_grid, 256, 2 * STAGE_BYTES>>>(featb, Wt1b, bt1, tbuf, nullptr, n, IN, 0);
    zero2_k<<<1, 256>>>(musum, varsum, D);
    bnstat_k<<<100, 256>>>(tbuf, musum, varsum, n);
    bnapply_k<<<(nd + 255) / 256, 256>>>(tbuf, musum, varsum, gamma, beta, tb, n);
    zerohtail_k<<<(tail + 255) / 256, 256>>>(tb, nd, ndpad);
    gemm_bf16_k<<<gemm_grid, 256, 2 * STAGE_BYTES>>>(tb, Wt2b, bt2, nullptr, transb, n, D, 0);
    zerohtail_k<<<(tail + 255) / 256, 256>>>(transb, nd, ndpad);
    gemm_bf16_k<<<gemm_grid, 256, 2 * STAGE_BYTES>>>(transb, Wpb, bp, pbuf, nullptr, n, D, 0);
    zero2_k<<<(n + 255) / 256, 256>>>(s1, s2, n);
    zero_k<<<1, 32>>>(out, out_size);

    // ---- join: normalize both ----
    cudaStreamWaitEvent(0, evGCN, 0);
    dim3 norm_grid((npad * 32 + 255) / 256, 2);
    norml2_k<<<norm_grid, 256>>>(hbuf, zh, ze, pbuf, qh, qe, n, npad);
    cudaEventRecord(evNorm, 0);

    // ---- fork pos to sA, negsum on main ----
    cudaStreamWaitEvent(sA, evNorm, 0);
    gather_pos_k<<<node_warp_blocks, 256, 0, sA>>>(zh, qh, csrc, off, pos, n);
    cudaEventRecord(evPos, sA);

    dim3 neg_grid(nTI, 24);
    negfp8_k<<<neg_grid, 256, 98304>>>(ze, qe, s1, s2, n, nTI);

    // ---- join + fused mneg + loss ----
    cudaStreamWaitEvent(0, evPos, 0);
    mneg_loss_k<<<node_warp_blocks, 256>>>(s1, s2, pos, csrc, off, out, n);
}

// round 12
// speedup vs baseline: 1.1800x; 1.1800x over previous
#include <cuda_runtime.h>
#include <cuda_bf16.h>
#include <stdint.h>
#include <math.h>

#define NMAX 10240
#define EMAX 340000
#define D 256
#define INMAX 512
#define TEMP_INV 2.0f
#define LAM 1e-3f
#define BN_EPS 1e-5f

// ------------------------------ scratch (BSS zero-initialized) ------------------------------
__device__ __align__(16) float g_t[NMAX * D];
__device__ __align__(16) float g_h[NMAX * D];
__device__ __align__(16) float g_p[NMAX * D];
__device__ __align__(16) __nv_bfloat16 g_featb[NMAX * INMAX];
__device__ __align__(16) __nv_bfloat16 g_xwb[NMAX * D];
__device__ __align__(16) __nv_bfloat16 g_h1b[NMAX * D];
__device__ __align__(16) __nv_bfloat16 g_tb[NMAX * D];
__device__ __align__(16) __nv_bfloat16 g_transb[NMAX * D];
__device__ __align__(16) __nv_bfloat16 g_zh[NMAX * D];
__device__ __align__(16) __nv_bfloat16 g_qh[NMAX * D];
__device__ __align__(16) __nv_bfloat16 g_W1b[INMAX * D];
__device__ __align__(16) __nv_bfloat16 g_W2b[D * D];
__device__ __align__(16) __nv_bfloat16 g_Wt1b[INMAX * D];
__device__ __align__(16) __nv_bfloat16 g_Wt2b[D * D];
__device__ __align__(16) __nv_bfloat16 g_Wpb[D * D];
__device__ float g_degout[NMAX];
__device__ float g_degin[NMAX];
__device__ float g_rsd[NMAX];
__device__ int   g_cnt[NMAX];
__device__ int   g_off[NMAX + 1];
__device__ int   g_cur[NMAX];
__device__ int   g_csrc[EMAX];
__device__ float g_musum[D];
__device__ float g_varsum[D];
__device__ float g_s1[NMAX];
__device__ float g_s2[NMAX];
__device__ float g_pos[NMAX];

// ------------------------------ small kernels ------------------------------
__global__ void zero2_k(float* a, float* b, int n) {
    int i = blockIdx.x * blockDim.x + threadIdx.x;
    if (i < n) { a[i] = 0.f; b[i] = 0.f; }
}
__global__ void zero3_k(float* a, float* b, int* c, int n) {
    int i = blockIdx.x * blockDim.x + threadIdx.x;
    if (i < n) { a[i] = 0.f; b[i] = 0.f; c[i] = 0; }
}
__global__ void zero_k(float* p, int n) {
    int i = blockIdx.x * blockDim.x + threadIdx.x;
    if (i < n) p[i] = 0.f;
}

__global__ void f2b_k(const float* __restrict__ x, __nv_bfloat16* __restrict__ y, int n) {
    int i = blockIdx.x * blockDim.x + threadIdx.x;
    if (i < n) y[i] = __float2bfloat16(x[i]);
}

__global__ void wconvall_k(const float* W1, const float* Wt1,
                           const float* W2, const float* Wt2, const float* Wp,
                           __nv_bfloat16* W1b, __nv_bfloat16* Wt1b,
                           __nv_bfloat16* W2b, __nv_bfloat16* Wt2b,
                           __nv_bfloat16* Wpb) {
    int i = blockIdx.x * blockDim.x + threadIdx.x;
    const float* W; __nv_bfloat16* O; int K, li;
    if (i < 131072)        { W = W1;  O = W1b;  K = 512; li = i; }
    else if (i < 262144)   { W = Wt1; O = Wt1b; K = 512; li = i - 131072; }
    else if (i < 327680)   { W = W2;  O = W2b;  K = 256; li = i - 262144; }
    else if (i < 393216)   { W = Wt2; O = Wt2b; K = 256; li = i - 327680; }
    else if (i < 458752)   { W = Wp;  O = Wpb;  K = 256; li = i - 393216; }
    else return;
    int k = li >> 8, n = li & 255;
    O[n * K + k] = __float2bfloat16(W[(size_t)k * 256 + n]);
}

__global__ void degree_k(const int* __restrict__ src, const int* __restrict__ dst,
                         float* dout, float* din, int* cnt, int e) {
    int i = blockIdx.x * blockDim.x + threadIdx.x;
    if (i < e) {
        atomicAdd(&dout[src[i]], 1.f);
        atomicAdd(&din[dst[i]], 1.f);
        atomicAdd(&cnt[dst[i]], 1);
    }
}

__global__ void rsdcur_k(const float* __restrict__ dout, float* rsd, int* cur, int n) {
    int i = blockIdx.x * blockDim.x + threadIdx.x;
    if (i < n) { rsd[i] = rsqrtf(dout[i]); cur[i] = 0; }
}

__global__ void scan_k(const int* __restrict__ cnt, int* off, int n) {
    __shared__ int ts[1024];
    int t = threadIdx.x;
    int L = (n + 1023) >> 10;
    int b = t * L, eidx = min(b + L, n);
    int s = 0;
    for (int i = b; i < eidx; i++) s += cnt[i];
    ts[t] = s;
    __syncthreads();
    for (int d2 = 1; d2 < 1024; d2 <<= 1) {
        int v = (t >= d2) ? ts[t - d2] : 0;
        __syncthreads();
        ts[t] += v;
        __syncthreads();
    }
    int base = (t == 0) ? 0 : ts[t - 1];
    for (int i = b; i < eidx; i++) { off[i] = base; base += cnt[i]; }
    if (t == 1023) off[n] = ts[1023];
}

__global__ void fillcsr_k(const int* __restrict__ src, const int* __restrict__ dst,
                          const int* __restrict__ off, int* cur, int* csrc, int e) {
    int i = blockIdx.x * blockDim.x + threadIdx.x;
    if (i < e) {
        int d = dst[i];
        int p = off[d] + atomicAdd(&cur[d], 1);
        csrc[p] = src[i];
    }
}

__global__ void gather_agg_k(const __nv_bfloat16* __restrict__ xw,
                             const int* __restrict__ csrc, const int* __restrict__ off,
                             const float* __restrict__ rsd, const float* __restrict__ din,
                             const float* __restrict__ bias,
                             float* outf, __nv_bfloat16* outh, int n, int relu) {
    int d = (blockIdx.x * blockDim.x + threadIdx.x) >> 5;
    int lane = threadIdx.x & 31;
    if (d >= n) return;
    float acc[8] = {};
    int p0 = off[d], p1 = off[d + 1];
    int p = p0;
    for (; p + 4 <= p1; p += 4) {
        int s0 = __ldg(csrc + p), s1i = __ldg(csrc + p + 1);
        int s2i = __ldg(csrc + p + 2), s3i = __ldg(csrc + p + 3);
        float w0 = rsd[s0], w1 = rsd[s1i], w2 = rsd[s2i], w3 = rsd[s3i];
        uint4 v0 = *((const uint4*)(xw + (size_t)s0 * D) + lane);
        uint4 v1 = *((const uint4*)(xw + (size_t)s1i * D) + lane);
        uint4 v2 = *((const uint4*)(xw + (size_t)s2i * D) + lane);
        uint4 v3 = *((const uint4*)(xw + (size_t)s3i * D) + lane);
        const __nv_bfloat16* h0 = (const __nv_bfloat16*)&v0;
        const __nv_bfloat16* h1 = (const __nv_bfloat16*)&v1;
        const __nv_bfloat16* h2 = (const __nv_bfloat16*)&v2;
        const __nv_bfloat16* h3 = (const __nv_bfloat16*)&v3;
#pragma unroll
        for (int k = 0; k < 8; k++)
            acc[k] += __bfloat162float(h0[k]) * w0 + __bfloat162float(h1[k]) * w1 +
                      __bfloat162float(h2[k]) * w2 + __bfloat162float(h3[k]) * w3;
    }
    for (; p < p1; p++) {
        int s = __ldg(csrc + p);
        float w = rsd[s];
        uint4 v = *((const uint4*)(xw + (size_t)s * D) + lane);
        const __nv_bfloat16* hv = (const __nv_bfloat16*)&v;
#pragma unroll
        for (int k = 0; k < 8; k++) acc[k] += __bfloat162float(hv[k]) * w;
    }
    float sc = rsqrtf(din[d]);
    int col = lane * 8;
    float o[8];
#pragma unroll
    for (int k = 0; k < 8; k++) {
        float v = acc[k] * sc + bias[col + k];
        o[k] = relu ? fmaxf(v, 0.f) : v;
    }
    if (outf) {
        float4* fr = (float4*)(outf + (size_t)d * D + col);
        fr[0] = make_float4(o[0], o[1], o[2], o[3]);
        fr[1] = make_float4(o[4], o[5], o[6], o[7]);
    }
    if (outh) {
        __nv_bfloat16 hb[8];
#pragma unroll
        for (int k = 0; k < 8; k++) hb[k] = __float2bfloat16(o[k]);
        *(uint4*)(outh + (size_t)d * D + col) = *(uint4*)hb;
    }
}

__global__ void bnstat_k(const float* __restrict__ t, float* musum, float* varsum, int M) {
    int col = threadIdx.x;
    int rpb = (M + gridDim.x - 1) / gridDim.x;
    int r0 = blockIdx.x * rpb;
    int r1 = min(r0 + rpb, M);
    float s = 0.f, s2 = 0.f;
    for (int r = r0; r < r1; r++) {
        float v = t[(size_t)r * D + col];
        s += v; s2 += v * v;
    }
    atomicAdd(&musum[col], s);
    atomicAdd(&varsum[col], s2);
}

__global__ void bnapply_k(const float* __restrict__ t, const float* __restrict__ musum,
                          const float* __restrict__ varsum,
                          const float* __restrict__ gamma, const float* __restrict__ beta,
                          __nv_bfloat16* th, int M) {
    int i = blockIdx.x * blockDim.x + threadIdx.x;
    if (i < M * D) {
        int c = i & (D - 1);
        float mu = musum[c] / M;
        float var = varsum[c] / M - mu * mu;
        float v = (t[i] - mu) * rsqrtf(var + BN_EPS) * gamma[c] + beta[c];
        th[i] = __float2bfloat16(fmaxf(v, 0.f));
    }
}

// normalize both h->zh and p->qh (bf16 only); rows >= n stay BSS-zero (never written)
__global__ void norml2_k(const float* __restrict__ x0, __nv_bfloat16* __restrict__ zh0,
                         const float* __restrict__ x1, __nv_bfloat16* __restrict__ zh1,
                         int M) {
    const float* x = blockIdx.y ? x1 : x0;
    __nv_bfloat16* zh = blockIdx.y ? zh1 : zh0;
    int row = (blockIdx.x * blockDim.x + threadIdx.x) >> 5;
    int lane = threadIdx.x & 31;
    if (row >= M) return;
    const float* xr = x + (size_t)row * D;
    float s = 0.f;
#pragma unroll
    for (int c = 0; c < D / 32; c++) {
        float v = xr[lane + 32 * c];
        s += v * v;
    }
#pragma unroll
    for (int o = 16; o > 0; o >>= 1) s += __shfl_xor_sync(0xffffffffu, s, o);
    float inv = 1.f / fmaxf(sqrtf(s), 1e-12f);
    __nv_bfloat16* hr = zh + (size_t)row * D;
#pragma unroll
    for (int c = 0; c < D / 32; c++) {
        int f = lane + 32 * c;
        hr[f] = __float2bfloat16(xr[f] * inv);
    }
}

__global__ void gather_pos_k(const __nv_bfloat16* __restrict__ zh,
                             const __nv_bfloat16* __restrict__ qh,
                             const int* __restrict__ csrc, const int* __restrict__ off,
                             float* pos, int n) {
    int d = (blockIdx.x * blockDim.x + threadIdx.x) >> 5;
    int lane = threadIdx.x & 31;
    if (d >= n) return;
    uint4 qv = *((const uint4*)(qh + (size_t)d * D) + lane);
    const __nv_bfloat16* qe = (const __nv_bfloat16*)&qv;
    float qf[8];
#pragma unroll
    for (int k = 0; k < 8; k++) qf[k] = __bfloat162float(qe[k]);
    float sz[8] = {};
    int p0 = off[d], p1 = off[d + 1];
    int p = p0;
    for (; p + 4 <= p1; p += 4) {
        int s0 = __ldg(csrc + p), s1i = __ldg(csrc + p + 1);
        int s2i = __ldg(csrc + p + 2), s3i = __ldg(csrc + p + 3);
        uint4 v0 = *((const uint4*)(zh + (size_t)s0 * D) + lane);
        uint4 v1 = *((const uint4*)(zh + (size_t)s1i * D) + lane);
        uint4 v2 = *((const uint4*)(zh + (size_t)s2i * D) + lane);
        uint4 v3 = *((const uint4*)(zh + (size_t)s3i * D) + lane);
        const __nv_bfloat16* h0 = (const __nv_bfloat16*)&v0;
        const __nv_bfloat16* h1 = (const __nv_bfloat16*)&v1;
        const __nv_bfloat16* h2 = (const __nv_bfloat16*)&v2;
        const __nv_bfloat16* h3 = (const __nv_bfloat16*)&v3;
#pragma unroll
        for (int k = 0; k < 8; k++)
            sz[k] += __bfloat162float(h0[k]) + __bfloat162float(h1[k]) +
                     __bfloat162float(h2[k]) + __bfloat162float(h3[k]);
    }
    for (; p < p1; p++) {
        int s = __ldg(csrc + p);
        uint4 v = *((const uint4*)(zh + (size_t)s * D) + lane);
        const __nv_bfloat16* hv = (const __nv_bfloat16*)&v;
#pragma unroll
        for (int k = 0; k < 8; k++) sz[k] += __bfloat162float(hv[k]);
    }
    float dot = 0.f;
#pragma unroll
    for (int k = 0; k < 8; k++) dot += sz[k] * qf[k];
#pragma unroll
    for (int o = 16; o > 0; o >>= 1) dot += __shfl_xor_sync(0xffffffffu, dot, o);
    if (lane == 0) pos[d] = dot * TEMP_INV;
}

__global__ void mneg_loss_k(const float* __restrict__ s1, const float* __restrict__ s2,
                            const float* __restrict__ pos,
                            const int* __restrict__ csrc, const int* __restrict__ off,
                            float* out, int n) {
    __shared__ float ws[8];
    int tid = threadIdx.x;
    int lane = tid & 31, warp = tid >> 5;
    int d = (blockIdx.x * blockDim.x + tid) >> 5;
    float contrib = 0.f;
    if (d < n) {
        float base = s1[d];
        float acc = 0.f;
        int p0 = off[d], p1 = off[d + 1];
        for (int p = p0 + lane; p < p1; p += 32)
            acc += __logf(base + LAM * s2[__ldg(csrc + p)]);
#pragma unroll
        for (int o = 16; o > 0; o >>= 1) acc += __shfl_xor_sync(0xffffffffu, acc, o);
        if (lane == 0) contrib = (acc - pos[d]) / (float)(p1 - p0);
    }
    if (lane == 0) ws[warp] = contrib;
    __syncthreads();
    if (tid == 0) {
        float t = 0.f;
#pragma unroll
        for (int w = 0; w < 8; w++) t += ws[w];
        atomicAdd(out, t / n);
    }
}

// ---------------- mma helpers ----------------
__device__ __forceinline__ void ldsm4(uint32_t addr, uint32_t& r0, uint32_t& r1,
                                      uint32_t& r2, uint32_t& r3) {
    asm volatile("ldmatrix.sync.aligned.m8n8.x4.shared.b16 {%0,%1,%2,%3}, [%4];"
                 : "=r"(r0), "=r"(r1), "=r"(r2), "=r"(r3) : "r"(addr));
}
__device__ __forceinline__ void mma16816(float* c, const uint32_t* a,
                                         uint32_t b0, uint32_t b1) {
    asm volatile(
        "mma.sync.aligned.m16n8k16.row.col.f32.bf16.bf16.f32 "
        "{%0,%1,%2,%3}, {%4,%5,%6,%7}, {%8,%9}, {%0,%1,%2,%3};"
        : "+f"(c[0]), "+f"(c[1]), "+f"(c[2]), "+f"(c[3])
        : "r"(a[0]), "r"(a[1]), "r"(a[2]), "r"(a[3]), "r"(b0), "r"(b1));
}
__device__ __forceinline__ void cp16(uint32_t saddr, const void* g) {
    asm volatile("cp.async.cg.shared.global [%0], [%1], 16;"
                 :: "r"(saddr), "l"(g) : "memory");
}
__device__ __forceinline__ void loadB64(uint32_t sdst, const __nv_bfloat16* Bg,
                                        int k0, int ldb, int tid) {
#pragma unroll
    for (int t = 0; t < 4; t++) {
        int c = tid + t * 256;
        int row = c >> 3, ch = c & 7;
        uint32_t off = (uint32_t)(row * 128 + ((ch ^ (row & 7)) << 4));
        cp16(sdst + off, Bg + (size_t)row * ldb + k0 + ch * 8);
    }
    asm volatile("cp.async.commit_group;" ::: "memory");
}

#define STAGE_BYTES 32768

// ---------------- bf16 tensor GEMM (pipelined): C = A[Mpad,K] @ Wt[256,K]^T ----------------
__global__ __launch_bounds__(256, 2) void gemm_bf16_k(
    const __nv_bfloat16* __restrict__ A, const __nv_bfloat16* __restrict__ Wt,
    const float* __restrict__ bias, float* __restrict__ Cf,
    __nv_bfloat16* __restrict__ Ch, int M, int K, int relu) {
    extern __shared__ char dsm[];
    uint32_t sbase = (uint32_t)__cvta_generic_to_shared(dsm);
    int tid = threadIdx.x;
    int lane = tid & 31, warp = tid >> 5;
    int wi = warp >> 1, wj = warp & 1;
    int i0 = blockIdx.x * 128, j0 = blockIdx.y * 128;

    int a_row = (lane & 15);
    int a_chsel = (lane >> 4);
    int b_row = (lane & 7) + ((lane >> 4) & 1) * 8;
    int b_chsel = ((lane >> 3) & 1);

    const __nv_bfloat16* Ag = A + (size_t)i0 * K;
    const __nv_bfloat16* Bg = Wt + (size_t)j0 * K;

    float acc[2][8][4];
#pragma unroll
    for (int x = 0; x < 2; x++)
#pragma unroll
        for (int y = 0; y < 8; y++)
#pragma unroll
            for (int v = 0; v < 4; v++) acc[x][y][v] = 0.f;

    int KT = K >> 6;
    loadB64(sbase, Ag, 0, K, tid);
    loadB64(sbase + 16384, Bg, 0, K, tid);
    for (int kt = 0; kt < KT; kt++) {
        asm volatile("cp.async.wait_group 0;" ::: "memory");
        __syncthreads();
        if (kt + 1 < KT) {
            uint32_t sa = sbase + ((kt + 1) & 1) * STAGE_BYTES;
            loadB64(sa, Ag, (kt + 1) * 64, K, tid);
            loadB64(sa + 16384, Bg, (kt + 1) * 64, K, tid);
        }
        uint32_t sAu = sbase + (kt & 1) * STAGE_BYTES;
        uint32_t sBu = sAu + 16384;
#pragma unroll
        for (int ks = 0; ks < 4; ks++) {
            uint32_t afr[2][4];
#pragma unroll
            for (int mt = 0; mt < 2; mt++) {
                int row = wi * 32 + mt * 16 + a_row;
                int ch = ks * 2 + a_chsel;
                uint32_t addr = sAu + (uint32_t)(row * 128 + ((ch ^ (row & 7)) << 4));
                ldsm4(addr, afr[mt][0], afr[mt][1], afr[mt][2], afr[mt][3]);
            }
#pragma unroll
            for (int p = 0; p < 4; p++) {
                int nrow = wj * 64 + p * 16 + b_row;
                int ch = ks * 2 + b_chsel;
                uint32_t addr = sBu + (uint32_t)(nrow * 128 + ((ch ^ (nrow & 7)) << 4));
                uint32_t bf0, bf1, bf2, bf3;
                ldsm4(addr, bf0, bf1, bf2, bf3);
#pragma unroll
                for (int mt = 0; mt < 2; mt++) {
                    mma16816(acc[mt][2 * p], afr[mt], bf0, bf1);
                    mma16816(acc[mt][2 * p + 1], afr[mt], bf2, bf3);
                }
            }
        }
        __syncthreads();
    }
#pragma unroll
    for (int mt = 0; mt < 2; mt++) {
        int r0 = i0 + wi * 32 + mt * 16 + (lane >> 2);
#pragma unroll
        for (int nt = 0; nt < 8; nt++) {
            int col = j0 + wj * 64 + nt * 8 + (lane & 3) * 2;
            float b0 = bias ? bias[col] : 0.f;
            float b1 = bias ? bias[col + 1] : 0.f;
            float v0 = acc[mt][nt][0] + b0, v1 = acc[mt][nt][1] + b1;
            float v2 = acc[mt][nt][2] + b0, v3 = acc[mt][nt][3] + b1;
            if (relu) {
                v0 = fmaxf(v0, 0.f); v1 = fmaxf(v1, 0.f);
                v2 = fmaxf(v2, 0.f); v3 = fmaxf(v3, 0.f);
            }
            if (r0 < M) {
                if (Cf) { Cf[(size_t)r0 * D + col] = v0; Cf[(size_t)r0 * D + col + 1] = v1; }
                if (Ch) {
                    Ch[(size_t)r0 * D + col] = __float2bfloat16(v0);
                    Ch[(size_t)r0 * D + col + 1] = __float2bfloat16(v1);
                }
            }
            int r1 = r0 + 8;
            if (r1 < M) {
                if (Cf) { Cf[(size_t)r1 * D + col] = v2; Cf[(size_t)r1 * D + col + 1] = v3; }
                if (Ch) {
                    Ch[(size_t)r1 * D + col] = __float2bfloat16(v2);
                    Ch[(size_t)r1 * D + col + 1] = __float2bfloat16(v3);
                }
            }
        }
    }
}

// ---------------- fused dual negsum (bf16 HMMA) ----------------
__global__ __launch_bounds__(256, 2) void negmma2_k(
    const __nv_bfloat16* __restrict__ Z, const __nv_bfloat16* __restrict__ Q,
    float* __restrict__ s1, float* __restrict__ s2, int n, int nJT) {
    extern __shared__ char dsm[];
    uint32_t aBase = (uint32_t)__cvta_generic_to_shared(dsm);        // 65536 B
    uint32_t bBase = aBase + 65536;                                   // 2 x 16384 B
    int tid = threadIdx.x;
    int lane = tid & 31, warp = tid >> 5;
    int wi = warp >> 1, wj = warp & 1;
    int i0 = blockIdx.x * 128;

    int a_row = (lane & 15);
    int a_chsel = (lane >> 4);
    int b_row = (lane & 7) + ((lane >> 4) & 1) * 8;
    int b_chsel = ((lane >> 3) & 1);

#pragma unroll
    for (int t = 0; t < 16; t++) {
        int c = tid + t * 256;
        int blk = c >> 10, idx = c & 1023;
        int row = idx >> 3, ch = idx & 7;
        uint32_t off = (uint32_t)(blk * 16384 + row * 128 + ((ch ^ (row & 7)) << 4));
        cp16(aBase + off, Z + (size_t)(i0 + row) * D + blk * 64 + ch * 8);
    }
    asm volatile("cp.async.commit_group;" ::: "memory");

    float rs[2][2][2];
#pragma unroll
    for (int a = 0; a < 2; a++)
#pragma unroll
        for (int b = 0; b < 2; b++)
#pragma unroll
            for (int c = 0; c < 2; c++) rs[a][b][c] = 0.f;

    for (int jt = blockIdx.y; jt < nJT; jt += gridDim.y) {
        int j0 = jt * 128;
#pragma unroll 1
        for (int sel = 0; sel < 2; sel++) {
            const __nv_bfloat16* Bg = (sel ? Q : Z) + (size_t)j0 * D;
            loadB64(bBase, Bg, 0, D, tid);
            float acc[2][8][4];
#pragma unroll
            for (int x = 0; x < 2; x++)
#pragma unroll
                for (int y = 0; y < 8; y++)
#pragma unroll
                    for (int v = 0; v < 4; v++) acc[x][y][v] = 0.f;

#pragma unroll
            for (int kt = 0; kt < 4; kt++) {
                asm volatile("cp.async.wait_group 0;" ::: "memory");
                __syncthreads();
                if (kt < 3) loadB64(bBase + ((kt + 1) & 1) * 16384, Bg, (kt + 1) * 64, D, tid);
                uint32_t sAu = aBase + kt * 16384;
                uint32_t sBu = bBase + (kt & 1) * 16384;
#pragma unroll
                for (int ks = 0; ks < 4; ks++) {
                    uint32_t afr[2][4];
#pragma unroll
                    for (int mt = 0; mt < 2; mt++) {
                        int row = wi * 32 + mt * 16 + a_row;
                        int ch = ks * 2 + a_chsel;
                        uint32_t addr = sAu + (uint32_t)(row * 128 + ((ch ^ (row & 7)) << 4));
                        ldsm4(addr, afr[mt][0], afr[mt][1], afr[mt][2], afr[mt][3]);
                    }
#pragma unroll
                    for (int p = 0; p < 4; p++) {
                        int nrow = wj * 64 + p * 16 + b_row;
                        int ch = ks * 2 + b_chsel;
                        uint32_t addr = sBu + (uint32_t)(nrow * 128 + ((ch ^ (nrow & 7)) << 4));
                        uint32_t bf0, bf1, bf2, bf3;
                        ldsm4(addr, bf0, bf1, bf2, bf3);
#pragma unroll
                        for (int mt = 0; mt < 2; mt++) {
                            mma16816(acc[mt][2 * p], afr[mt], bf0, bf1);
                            mma16816(acc[mt][2 * p + 1], afr[mt], bf2, bf3);
                        }
                    }
                }
                __syncthreads();
            }
#pragma unroll
            for (int mt = 0; mt < 2; mt++) {
#pragma unroll
                for (int nt = 0; nt < 8; nt++) {
                    int j = j0 + wj * 64 + nt * 8 + (lane & 3) * 2;
                    float e0 = (j < n) ? __expf(acc[mt][nt][0] * TEMP_INV) : 0.f;
                    float e1 = (j + 1 < n) ? __expf(acc[mt][nt][1] * TEMP_INV) : 0.f;
                    float e2 = (j < n) ? __expf(acc[mt][nt][2] * TEMP_INV) : 0.f;
                    float e3 = (j + 1 < n) ? __expf(acc[mt][nt][3] * TEMP_INV) : 0.f;
                    rs[sel][mt][0] += e0 + e1;
                    rs[sel][mt][1] += e2 + e3;
                }
            }
        }
    }
#pragma unroll
    for (int sel = 0; sel < 2; sel++) {
        float* out = sel ? s2 : s1;
#pragma unroll
        for (int mt = 0; mt < 2; mt++) {
#pragma unroll
            for (int h = 0; h < 2; h++) {
                float v = rs[sel][mt][h];
                v += __shfl_xor_sync(0xffffffffu, v, 1);
                v += __shfl_xor_sync(0xffffffffu, v, 2);
                if ((lane & 3) == 0) {
                    int i = i0 + wi * 32 + mt * 16 + h * 8 + (lane >> 2);
                    if (i < n) atomicAdd(&out[i], v);
                }
            }
        }
    }
}

// ------------------------------ launcher ------------------------------
static float* symf(const void* s) { void* p = nullptr; cudaGetSymbolAddress(&p, s); return (float*)p; }
static int* symi(const void* s) { void* p = nullptr; cudaGetSymbolAddress(&p, s); return (int*)p; }
static __nv_bfloat16* symh(const void* s) { void* p = nullptr; cudaGetSymbolAddress(&p, s); return (__nv_bfloat16*)p; }

extern "C" void kernel_launch(void* const* d_in, const int* in_sizes, int n_in,
                              void* d_out, int out_size) {
    const float* feat  = (const float*)d_in[0];
    const float* W1    = (const float*)d_in[1];
    const float* b1    = (const float*)d_in[2];
    const float* W2    = (const float*)d_in[3];
    const float* b2    = (const float*)d_in[4];
    const float* Wt1   = (const float*)d_in[5];
    const float* bt1   = (const float*)d_in[6];
    const float* gamma = (const float*)d_in[7];
    const float* beta  = (const float*)d_in[8];
    const float* Wt2   = (const float*)d_in[9];
    const float* bt2   = (const float*)d_in[10];
    const float* Wp    = (const float*)d_in[11];
    const float* bp    = (const float*)d_in[12];
    const int*   src   = (const int*)d_in[13];
    const int*   dst   = (const int*)d_in[14];

    const int IN = 512;
    int n = in_sizes[0] / IN;
    int e = in_sizes[13];
    int nTI = (n + 127) / 128;

    float* tbuf = symf(g_t);
    float* hbuf = symf(g_h);
    float* pbuf = symf(g_p);
    __nv_bfloat16* featb = symh(g_featb);
    __nv_bfloat16* xwb = symh(g_xwb);
    __nv_bfloat16* h1b = symh(g_h1b);
    __nv_bfloat16* tb = symh(g_tb);
    __nv_bfloat16* transb = symh(g_transb);
    __nv_bfloat16* zh = symh(g_zh);
    __nv_bfloat16* qh = symh(g_qh);
    __nv_bfloat16* W1b = symh(g_W1b);
    __nv_bfloat16* W2b = symh(g_W2b);
    __nv_bfloat16* Wt1b = symh(g_Wt1b);
    __nv_bfloat16* Wt2b = symh(g_Wt2b);
    __nv_bfloat16* Wpb = symh(g_Wpb);
    float* dout = symf(g_degout);
    float* din  = symf(g_degin);
    float* rsd  = symf(g_rsd);
    int* cnt = symi(g_cnt);
    int* off = symi(g_off);
    int* cur = symi(g_cur);
    int* csrc = symi(g_csrc);
    float* musum = symf(g_musum);
    float* varsum = symf(g_varsum);
    float* s1 = symf(g_s1);
    float* s2 = symf(g_s2);
    float* pos = symf(g_pos);
    float* out = (float*)d_out;

    int nd = n * D;
    dim3 gemm_grid(nTI, 2);
    int node_warp_blocks = (n * 32 + 255) / 256;

    static cudaStream_t sA = nullptr, sB = nullptr;
    static cudaEvent_t evStart, evRoot, evCSR, evGCN, evNorm, evPos;
    if (sA == nullptr) {
        cudaStreamCreateWithFlags(&sA, cudaStreamNonBlocking);
        cudaStreamCreateWithFlags(&sB, cudaStreamNonBlocking);
        cudaEventCreateWithFlags(&evStart, cudaEventDisableTiming);
        cudaEventCreateWithFlags(&evRoot, cudaEventDisableTiming);
        cudaEventCreateWithFlags(&evCSR, cudaEventDisableTiming);
        cudaEventCreateWithFlags(&evGCN, cudaEventDisableTiming);
        cudaEventCreateWithFlags(&evNorm, cudaEventDisableTiming);
        cudaEventCreateWithFlags(&evPos, cudaEventDisableTiming);
        cudaFuncSetAttribute(gemm_bf16_k, cudaFuncAttributeMaxDynamicSharedMemorySize, 2 * STAGE_BYTES);
        cudaFuncSetAttribute(negmma2_k, cudaFuncAttributeMaxDynamicSharedMemorySize, 98304);
    }

    // ---- fork CSR chain to sB ----
    cudaEventRecord(evStart, 0);
    cudaStreamWaitEvent(sB, evStart, 0);
    zero3_k<<<(n + 255) / 256, 256, 0, sB>>>(dout, din, cnt, n);
    degree_k<<<(e + 255) / 256, 256, 0, sB>>>(src, dst, dout, din, cnt, e);
    rsdcur_k<<<(n + 255) / 256, 256, 0, sB>>>(dout, rsd, cur, n);
    scan_k<<<1, 1024, 0, sB>>>(cnt, off, n);
    fillcsr_k<<<(e + 255) / 256, 256, 0, sB>>>(src, dst, off, cur, csrc, e);
    cudaEventRecord(evCSR, sB);

    // ---- main: conversions (pad rows of featb remain BSS-zero) ----
    f2b_k<<<(n * IN + 255) / 256, 256>>>(feat, featb, n * IN);
    wconvall_k<<<(458752 + 255) / 256, 256>>>(W1, Wt1, W2, Wt2, Wp,
                                              W1b, Wt1b, W2b, Wt2b, Wpb);
    cudaEventRecord(evRoot, 0);

    // ---- fork GCN branch to sA (tails of h1b stay BSS-zero) ----
    cudaStreamWaitEvent(sA, evRoot, 0);
    gemm_bf16_k<<<gemm_grid, 256, 2 * STAGE_BYTES, sA>>>(featb, W1b, nullptr, nullptr, xwb, n, IN, 0);
    cudaStreamWaitEvent(sA, evCSR, 0);
    gather_agg_k<<<node_warp_blocks, 256, 0, sA>>>(xwb, csrc, off, rsd, din, b1, nullptr, h1b, n, 1);
    gemm_bf16_k<<<gemm_grid, 256, 2 * STAGE_BYTES, sA>>>(h1b, W2b, nullptr, nullptr, xwb, n, D, 0);
    gather_agg_k<<<node_warp_blocks, 256, 0, sA>>>(xwb, csrc, off, rsd, din, b2, hbuf, nullptr, n, 0);
    cudaEventRecord(evGCN, sA);

    // ---- main: target MLP branch (tails of tb/transb stay BSS-zero) ----
    gemm_bf16_k<<<gemm_grid, 256, 2 * STAGE_BYTES>>>(featb, Wt1b, bt1, tbuf, nullptr, n, IN, 0);
    zero2_k<<<1, 256>>>(musum, varsum, D);
    bnstat_k<<<100, 256>>>(tbuf, musum, varsum, n);
    bnapply_k<<<(nd + 255) / 256, 256>>>(tbuf, musum, varsum, gamma, beta, tb, n);
    gemm_bf16_k<<<gemm_grid, 256, 2 * STAGE_BYTES>>>(tb, Wt2b, bt2, nullptr, transb, n, D, 0);
    gemm_bf16_k<<<gemm_grid, 256, 2 * STAGE_BYTES>>>(transb, Wpb, bp, pbuf, nullptr, n, D, 0);
    zero2_k<<<(n + 255) / 256, 256>>>(s1, s2, n);
    zero_k<<<1, 32>>>(out, out_size);

    // ---- join: normalize both (zh/qh pad rows stay BSS-zero) ----
    cudaStreamWaitEvent(0, evGCN, 0);
    dim3 norm_grid((n * 32 + 255) / 256, 2);
    norml2_k<<<norm_grid, 256>>>(hbuf, zh, pbuf, qh, n);
    cudaEventRecord(evNorm, 0);

    // ---- fork pos to sA, negsum on main ----
    cudaStreamWaitEvent(sA, evNorm, 0);
    gather_pos_k<<<node_warp_blocks, 256, 0, sA>>>(zh, qh, csrc, off, pos, n);
    cudaEventRecord(evPos, sA);

    dim3 neg_grid(nTI, 24);
    negmma2_k<<<neg_grid, 256, 98304>>>(zh, qh, s1, s2, n, nTI);

    // ---- join + fused mneg + loss ----
    cudaStreamWaitEvent(0, evPos, 0);
    mneg_loss_k<<<node_warp_blocks, 256>>>(s1, s2, pos, csrc, off, out, n);
}

// round 13
// speedup vs baseline: 1.2029x; 1.0194x over previous
#include <cuda_runtime.h>
#include <cuda_bf16.h>
#include <stdint.h>
#include <math.h>

#define NMAX 10240
#define EMAX 340000
#define D 256
#define INMAX 512
#define TEMP_INV 2.0f
#define LAM 1e-3f
#define BN_EPS 1e-5f

// ------------------------------ scratch (BSS zero-initialized) ------------------------------
__device__ __align__(16) float g_t[NMAX * D];
__device__ __align__(16) float g_p[NMAX * D];
__device__ __align__(16) __nv_bfloat16 g_featb[NMAX * INMAX];
__device__ __align__(16) __nv_bfloat16 g_xwb[NMAX * D];
__device__ __align__(16) __nv_bfloat16 g_h1b[NMAX * D];
__device__ __align__(16) __nv_bfloat16 g_tb[NMAX * D];
__device__ __align__(16) __nv_bfloat16 g_transb[NMAX * D];
__device__ __align__(16) __nv_bfloat16 g_zh[NMAX * D];
__device__ __align__(16) __nv_bfloat16 g_qh[NMAX * D];
__device__ __align__(16) __nv_bfloat16 g_Wcomb[INMAX * INMAX];  // [512 N][512 K]: rows 0-255 W1^T, 256-511 Wt1^T
__device__ __align__(16) __nv_bfloat16 g_W2b[D * D];
__device__ __align__(16) __nv_bfloat16 g_Wt2b[D * D];
__device__ __align__(16) __nv_bfloat16 g_Wpb[D * D];
__device__ float g_degout[NMAX];
__device__ float g_degin[NMAX];
__device__ float g_rsd[NMAX];
__device__ int   g_cnt[NMAX];
__device__ int   g_off[NMAX + 1];
__device__ int   g_cur[NMAX];
__device__ int   g_csrc[EMAX];
__device__ float g_musum[D];
__device__ float g_varsum[D];
__device__ float g_s1[NMAX];
__device__ float g_s2[NMAX];
__device__ float g_pos[NMAX];

// ------------------------------ small kernels ------------------------------
__global__ void zero2_k(float* a, float* b, int n) {
    int i = blockIdx.x * blockDim.x + threadIdx.x;
    if (i < n) { a[i] = 0.f; b[i] = 0.f; }
}
__global__ void zero3_k(float* a, float* b, int* c, int n) {
    int i = blockIdx.x * blockDim.x + threadIdx.x;
    if (i < n) { a[i] = 0.f; b[i] = 0.f; c[i] = 0; }
}
__global__ void zero_k(float* p, int n) {
    int i = blockIdx.x * blockDim.x + threadIdx.x;
    if (i < n) p[i] = 0.f;
}

__global__ void f2b_k(const float* __restrict__ x, __nv_bfloat16* __restrict__ y, int n) {
    int i = blockIdx.x * blockDim.x + threadIdx.x;
    if (i < n) y[i] = __float2bfloat16(x[i]);
}

__global__ void wconvall_k(const float* W1, const float* Wt1,
                           const float* W2, const float* Wt2, const float* Wp,
                           __nv_bfloat16* W1c, __nv_bfloat16* Wt1c,
                           __nv_bfloat16* W2b, __nv_bfloat16* Wt2b,
                           __nv_bfloat16* Wpb) {
    int i = blockIdx.x * blockDim.x + threadIdx.x;
    const float* W; __nv_bfloat16* O; int K, li;
    if (i < 131072)        { W = W1;  O = W1c;  K = 512; li = i; }
    else if (i < 262144)   { W = Wt1; O = Wt1c; K = 512; li = i - 131072; }
    else if (i < 327680)   { W = W2;  O = W2b;  K = 256; li = i - 262144; }
    else if (i < 393216)   { W = Wt2; O = Wt2b; K = 256; li = i - 327680; }
    else if (i < 458752)   { W = Wp;  O = Wpb;  K = 256; li = i - 393216; }
    else return;
    int k = li >> 8, n = li & 255;
    O[n * K + k] = __float2bfloat16(W[(size_t)k * 256 + n]);
}

__global__ void degree_k(const int* __restrict__ src, const int* __restrict__ dst,
                         float* dout, float* din, int* cnt, int e) {
    int i = blockIdx.x * blockDim.x + threadIdx.x;
    if (i < e) {
        atomicAdd(&dout[src[i]], 1.f);
        atomicAdd(&din[dst[i]], 1.f);
        atomicAdd(&cnt[dst[i]], 1);
    }
}

__global__ void rsdcur_k(const float* __restrict__ dout, float* rsd, int* cur, int n) {
    int i = blockIdx.x * blockDim.x + threadIdx.x;
    if (i < n) { rsd[i] = rsqrtf(dout[i]); cur[i] = 0; }
}

__global__ void scan_k(const int* __restrict__ cnt, int* off, int n) {
    __shared__ int ts[1024];
    int t = threadIdx.x;
    int L = (n + 1023) >> 10;
    int b = t * L, eidx = min(b + L, n);
    int s = 0;
    for (int i = b; i < eidx; i++) s += cnt[i];
    ts[t] = s;
    __syncthreads();
    for (int d2 = 1; d2 < 1024; d2 <<= 1) {
        int v = (t >= d2) ? ts[t - d2] : 0;
        __syncthreads();
        ts[t] += v;
        __syncthreads();
    }
    int base = (t == 0) ? 0 : ts[t - 1];
    for (int i = b; i < eidx; i++) { off[i] = base; base += cnt[i]; }
    if (t == 1023) off[n] = ts[1023];
}

__global__ void fillcsr_k(const int* __restrict__ src, const int* __restrict__ dst,
                          const int* __restrict__ off, int* cur, int* csrc, int e) {
    int i = blockIdx.x * blockDim.x + threadIdx.x;
    if (i < e) {
        int d = dst[i];
        int p = off[d] + atomicAdd(&cur[d], 1);
        csrc[p] = src[i];
    }
}

// gather agg, one warp per dst node, unroll-8; optional fused L2-normalize
__global__ void gather_agg_k(const __nv_bfloat16* __restrict__ xw,
                             const int* __restrict__ csrc, const int* __restrict__ off,
                             const float* __restrict__ rsd, const float* __restrict__ din,
                             const float* __restrict__ bias,
                             __nv_bfloat16* outh, int n, int relu, int norm) {
    int d = (blockIdx.x * blockDim.x + threadIdx.x) >> 5;
    int lane = threadIdx.x & 31;
    if (d >= n) return;
    float acc[8] = {};
    int p0 = off[d], p1 = off[d + 1];
    int p = p0;
    for (; p + 8 <= p1; p += 8) {
        int si[8];
#pragma unroll
        for (int u = 0; u < 8; u++) si[u] = __ldg(csrc + p + u);
        uint4 v[8];
#pragma unroll
        for (int u = 0; u < 8; u++) v[u] = *((const uint4*)(xw + (size_t)si[u] * D) + lane);
        float w[8];
#pragma unroll
        for (int u = 0; u < 8; u++) w[u] = rsd[si[u]];
#pragma unroll
        for (int u = 0; u < 8; u++) {
            const __nv_bfloat16* hv = (const __nv_bfloat16*)&v[u];
#pragma unroll
            for (int k = 0; k < 8; k++) acc[k] += __bfloat162float(hv[k]) * w[u];
        }
    }
    for (; p < p1; p++) {
        int s = __ldg(csrc + p);
        float w = rsd[s];
        uint4 vv = *((const uint4*)(xw + (size_t)s * D) + lane);
        const __nv_bfloat16* hv = (const __nv_bfloat16*)&vv;
#pragma unroll
        for (int k = 0; k < 8; k++) acc[k] += __bfloat162float(hv[k]) * w;
    }
    float sc = rsqrtf(din[d]);
    int col = lane * 8;
    float o[8];
#pragma unroll
    for (int k = 0; k < 8; k++) {
        float v = acc[k] * sc + bias[col + k];
        o[k] = relu ? fmaxf(v, 0.f) : v;
    }
    if (norm) {
        float ss = 0.f;
#pragma unroll
        for (int k = 0; k < 8; k++) ss += o[k] * o[k];
#pragma unroll
        for (int os = 16; os > 0; os >>= 1) ss += __shfl_xor_sync(0xffffffffu, ss, os);
        float inv = 1.f / fmaxf(sqrtf(ss), 1e-12f);
#pragma unroll
        for (int k = 0; k < 8; k++) o[k] *= inv;
    }
    __nv_bfloat16 hb[8];
#pragma unroll
    for (int k = 0; k < 8; k++) hb[k] = __float2bfloat16(o[k]);
    *(uint4*)(outh + (size_t)d * D + col) = *(uint4*)hb;
}

__global__ void bnstat_k(const float* __restrict__ t, float* musum, float* varsum, int M) {
    int col = threadIdx.x;
    int rpb = (M + gridDim.x - 1) / gridDim.x;
    int r0 = blockIdx.x * rpb;
    int r1 = min(r0 + rpb, M);
    float s = 0.f, s2 = 0.f;
    for (int r = r0; r < r1; r++) {
        float v = t[(size_t)r * D + col];
        s += v; s2 += v * v;
    }
    atomicAdd(&musum[col], s);
    atomicAdd(&varsum[col], s2);
}

__global__ void bnapply_k(const float* __restrict__ t, const float* __restrict__ musum,
                          const float* __restrict__ varsum,
                          const float* __restrict__ gamma, const float* __restrict__ beta,
                          __nv_bfloat16* th, int M) {
    int i = blockIdx.x * blockDim.x + threadIdx.x;
    if (i < M * D) {
        int c = i & (D - 1);
        float mu = musum[c] / M;
        float var = varsum[c] / M - mu * mu;
        float v = (t[i] - mu) * rsqrtf(var + BN_EPS) * gamma[c] + beta[c];
        th[i] = __float2bfloat16(fmaxf(v, 0.f));
    }
}

// single normalize x -> zh (bf16); rows >= n stay BSS-zero
__global__ void norml1_k(const float* __restrict__ x, __nv_bfloat16* __restrict__ zh, int M) {
    int row = (blockIdx.x * blockDim.x + threadIdx.x) >> 5;
    int lane = threadIdx.x & 31;
    if (row >= M) return;
    const float* xr = x + (size_t)row * D;
    float s = 0.f;
#pragma unroll
    for (int c = 0; c < D / 32; c++) {
        float v = xr[lane + 32 * c];
        s += v * v;
    }
#pragma unroll
    for (int o = 16; o > 0; o >>= 1) s += __shfl_xor_sync(0xffffffffu, s, o);
    float inv = 1.f / fmaxf(sqrtf(s), 1e-12f);
    __nv_bfloat16* hr = zh + (size_t)row * D;
#pragma unroll
    for (int c = 0; c < D / 32; c++) {
        int f = lane + 32 * c;
        hr[f] = __float2bfloat16(xr[f] * inv);
    }
}

__global__ void gather_pos_k(const __nv_bfloat16* __restrict__ zh,
                             const __nv_bfloat16* __restrict__ qh,
                             const int* __restrict__ csrc, const int* __restrict__ off,
                             float* pos, int n) {
    int d = (blockIdx.x * blockDim.x + threadIdx.x) >> 5;
    int lane = threadIdx.x & 31;
    if (d >= n) return;
    uint4 qv = *((const uint4*)(qh + (size_t)d * D) + lane);
    const __nv_bfloat16* qe = (const __nv_bfloat16*)&qv;
    float qf[8];
#pragma unroll
    for (int k = 0; k < 8; k++) qf[k] = __bfloat162float(qe[k]);
    float sz[8] = {};
    int p0 = off[d], p1 = off[d + 1];
    int p = p0;
    for (; p + 8 <= p1; p += 8) {
        int si[8];
#pragma unroll
        for (int u = 0; u < 8; u++) si[u] = __ldg(csrc + p + u);
        uint4 v[8];
#pragma unroll
        for (int u = 0; u < 8; u++) v[u] = *((const uint4*)(zh + (size_t)si[u] * D) + lane);
#pragma unroll
        for (int u = 0; u < 8; u++) {
            const __nv_bfloat16* hv = (const __nv_bfloat16*)&v[u];
#pragma unroll
            for (int k = 0; k < 8; k++) sz[k] += __bfloat162float(hv[k]);
        }
    }
    for (; p < p1; p++) {
        int s = __ldg(csrc + p);
        uint4 vv = *((const uint4*)(zh + (size_t)s * D) + lane);
        const __nv_bfloat16* hv = (const __nv_bfloat16*)&vv;
#pragma unroll
        for (int k = 0; k < 8; k++) sz[k] += __bfloat162float(hv[k]);
    }
    float dot = 0.f;
#pragma unroll
    for (int k = 0; k < 8; k++) dot += sz[k] * qf[k];
#pragma unroll
    for (int o = 16; o > 0; o >>= 1) dot += __shfl_xor_sync(0xffffffffu, dot, o);
    if (lane == 0) pos[d] = dot * TEMP_INV;
}

__global__ void mneg_loss_k(const float* __restrict__ s1, const float* __restrict__ s2,
                            const float* __restrict__ pos,
                            const int* __restrict__ csrc, const int* __restrict__ off,
                            float* out, int n) {
    __shared__ float ws[8];
    int tid = threadIdx.x;
    int lane = tid & 31, warp = tid >> 5;
    int d = (blockIdx.x * blockDim.x + tid) >> 5;
    float contrib = 0.f;
    if (d < n) {
        float base = s1[d];
        float acc = 0.f;
        int p0 = off[d], p1 = off[d + 1];
        for (int p = p0 + lane; p < p1; p += 32)
            acc += __logf(base + LAM * s2[__ldg(csrc + p)]);
#pragma unroll
        for (int o = 16; o > 0; o >>= 1) acc += __shfl_xor_sync(0xffffffffu, acc, o);
        if (lane == 0) contrib = (acc - pos[d]) / (float)(p1 - p0);
    }
    if (lane == 0) ws[warp] = contrib;
    __syncthreads();
    if (tid == 0) {
        float t = 0.f;
#pragma unroll
        for (int w = 0; w < 8; w++) t += ws[w];
        atomicAdd(out, t / n);
    }
}

// ---------------- mma helpers ----------------
__device__ __forceinline__ void ldsm4(uint32_t addr, uint32_t& r0, uint32_t& r1,
                                      uint32_t& r2, uint32_t& r3) {
    asm volatile("ldmatrix.sync.aligned.m8n8.x4.shared.b16 {%0,%1,%2,%3}, [%4];"
                 : "=r"(r0), "=r"(r1), "=r"(r2), "=r"(r3) : "r"(addr));
}
__device__ __forceinline__ void mma16816(float* c, const uint32_t* a,
                                         uint32_t b0, uint32_t b1) {
    asm volatile(
        "mma.sync.aligned.m16n8k16.row.col.f32.bf16.bf16.f32 "
        "{%0,%1,%2,%3}, {%4,%5,%6,%7}, {%8,%9}, {%0,%1,%2,%3};"
        : "+f"(c[0]), "+f"(c[1]), "+f"(c[2]), "+f"(c[3])
        : "r"(a[0]), "r"(a[1]), "r"(a[2]), "r"(a[3]), "r"(b0), "r"(b1));
}
__device__ __forceinline__ void cp16(uint32_t saddr, const void* g) {
    asm volatile("cp.async.cg.shared.global [%0], [%1], 16;"
                 :: "r"(saddr), "l"(g) : "memory");
}
__device__ __forceinline__ void loadB64(uint32_t sdst, const __nv_bfloat16* Bg,
                                        int k0, int ldb, int tid) {
#pragma unroll
    for (int t = 0; t < 4; t++) {
        int c = tid + t * 256;
        int row = c >> 3, ch = c & 7;
        uint32_t off = (uint32_t)(row * 128 + ((ch ^ (row & 7)) << 4));
        cp16(sdst + off, Bg + (size_t)row * ldb + k0 + ch * 8);
    }
    asm volatile("cp.async.commit_group;" ::: "memory");
}

#define STAGE_BYTES 32768

// shared mainloop for 128x128 bf16 gemm tile; acc produced in caller-visible array
#define GEMM_MAINLOOP(A_, B_, K_)                                                     \
    int KT = (K_) >> 6;                                                               \
    loadB64(sbase, (A_), 0, (K_), tid);                                               \
    loadB64(sbase + 16384, (B_), 0, (K_), tid);                                       \
    for (int kt = 0; kt < KT; kt++) {                                                 \
        asm volatile("cp.async.wait_group 0;" ::: "memory");                          \
        __syncthreads();                                                              \
        if (kt + 1 < KT) {                                                            \
            uint32_t sa = sbase + ((kt + 1) & 1) * STAGE_BYTES;                       \
            loadB64(sa, (A_), (kt + 1) * 64, (K_), tid);                              \
            loadB64(sa + 16384, (B_), (kt + 1) * 64, (K_), tid);                      \
        }                                                                             \
        uint32_t sAu = sbase + (kt & 1) * STAGE_BYTES;                                \
        uint32_t sBu = sAu + 16384;                                                   \
        _Pragma("unroll")                                                             \
        for (int ks = 0; ks < 4; ks++) {                                              \
            uint32_t afr[2][4];                                                       \
            _Pragma("unroll")                                                         \
            for (int mt = 0; mt < 2; mt++) {                                          \
                int row = wi * 32 + mt * 16 + a_row;                                  \
                int ch = ks * 2 + a_chsel;                                            \
                uint32_t addr = sAu + (uint32_t)(row * 128 + ((ch ^ (row & 7)) << 4));\
                ldsm4(addr, afr[mt][0], afr[mt][1], afr[mt][2], afr[mt][3]);          \
            }                                                                         \
            _Pragma("unroll")                                                         \
            for (int pp = 0; pp < 4; pp++) {                                          \
                int nrow = wj * 64 + pp * 16 + b_row;                                 \
                int ch = ks * 2 + b_chsel;                                            \
                uint32_t addr = sBu + (uint32_t)(nrow * 128 + ((ch ^ (nrow & 7)) << 4));\
                uint32_t bf0, bf1, bf2, bf3;                                          \
                ldsm4(addr, bf0, bf1, bf2, bf3);                                      \
                _Pragma("unroll")                                                     \
                for (int mt = 0; mt < 2; mt++) {                                      \
                    mma16816(acc[mt][2 * pp], afr[mt], bf0, bf1);                     \
                    mma16816(acc[mt][2 * pp + 1], afr[mt], bf2, bf3);                 \
                }                                                                     \
            }                                                                         \
        }                                                                             \
        __syncthreads();                                                              \
    }

// ---------------- bf16 tensor GEMM: C = A[Mpad,K] @ Wt[256,K]^T ----------------
__global__ __launch_bounds__(256, 2) void gemm_bf16_k(
    const __nv_bfloat16* __restrict__ A, const __nv_bfloat16* __restrict__ Wt,
    const float* __restrict__ bias, float* __restrict__ Cf,
    __nv_bfloat16* __restrict__ Ch, int M, int K, int relu) {
    extern __shared__ char dsm[];
    uint32_t sbase = (uint32_t)__cvta_generic_to_shared(dsm);
    int tid = threadIdx.x;
    int lane = tid & 31, warp = tid >> 5;
    int wi = warp >> 1, wj = warp & 1;
    int i0 = blockIdx.x * 128, j0 = blockIdx.y * 128;

    int a_row = (lane & 15);
    int a_chsel = (lane >> 4);
    int b_row = (lane & 7) + ((lane >> 4) & 1) * 8;
    int b_chsel = ((lane >> 3) & 1);

    const __nv_bfloat16* Ag = A + (size_t)i0 * K;
    const __nv_bfloat16* Bg = Wt + (size_t)j0 * K;

    float acc[2][8][4];
#pragma unroll
    for (int x = 0; x < 2; x++)
#pragma unroll
        for (int y = 0; y < 8; y++)
#pragma unroll
            for (int v = 0; v < 4; v++) acc[x][y][v] = 0.f;

    GEMM_MAINLOOP(Ag, Bg, K)

#pragma unroll
    for (int mt = 0; mt < 2; mt++) {
        int r0 = i0 + wi * 32 + mt * 16 + (lane >> 2);
#pragma unroll
        for (int nt = 0; nt < 8; nt++) {
            int col = j0 + wj * 64 + nt * 8 + (lane & 3) * 2;
            float b0 = bias ? bias[col] : 0.f;
            float b1 = bias ? bias[col + 1] : 0.f;
            float v0 = acc[mt][nt][0] + b0, v1 = acc[mt][nt][1] + b1;
            float v2 = acc[mt][nt][2] + b0, v3 = acc[mt][nt][3] + b1;
            if (relu) {
                v0 = fmaxf(v0, 0.f); v1 = fmaxf(v1, 0.f);
                v2 = fmaxf(v2, 0.f); v3 = fmaxf(v3, 0.f);
            }
            if (r0 < M) {
                if (Cf) { Cf[(size_t)r0 * D + col] = v0; Cf[(size_t)r0 * D + col + 1] = v1; }
                if (Ch) {
                    Ch[(size_t)r0 * D + col] = __float2bfloat16(v0);
                    Ch[(size_t)r0 * D + col + 1] = __float2bfloat16(v1);
                }
            }
            int r1 = r0 + 8;
            if (r1 < M) {
                if (Cf) { Cf[(size_t)r1 * D + col] = v2; Cf[(size_t)r1 * D + col + 1] = v3; }
                if (Ch) {
                    Ch[(size_t)r1 * D + col] = __float2bfloat16(v2);
                    Ch[(size_t)r1 * D + col + 1] = __float2bfloat16(v3);
                }
            }
        }
    }
}

// ---------------- dual-output gemm: featb @ Wcomb[512,512]^T ----------------
// cols 0..255 -> xwb (bf16, no bias); cols 256..511 -> tbuf (fp32, +bt1)
__global__ __launch_bounds__(256, 2) void gemm_dual_k(
    const __nv_bfloat16* __restrict__ A, const __nv_bfloat16* __restrict__ Wc,
    const float* __restrict__ bt1, __nv_bfloat16* __restrict__ Xh,
    float* __restrict__ Tf, int M, int K) {
    extern __shared__ char dsm[];
    uint32_t sbase = (uint32_t)__cvta_generic_to_shared(dsm);
    int tid = threadIdx.x;
    int lane = tid & 31, warp = tid >> 5;
    int wi = warp >> 1, wj = warp & 1;
    int i0 = blockIdx.x * 128, j0 = blockIdx.y * 128;

    int a_row = (lane & 15);
    int a_chsel = (lane >> 4);
    int b_row = (lane & 7) + ((lane >> 4) & 1) * 8;
    int b_chsel = ((lane >> 3) & 1);

    const __nv_bfloat16* Ag = A + (size_t)i0 * K;
    const __nv_bfloat16* Bg = Wc + (size_t)j0 * K;

    float acc[2][8][4];
#pragma unroll
    for (int x = 0; x < 2; x++)
#pragma unroll
        for (int y = 0; y < 8; y++)
#pragma unroll
            for (int v = 0; v < 4; v++) acc[x][y][v] = 0.f;

    GEMM_MAINLOOP(Ag, Bg, K)

    int isT = (j0 >= 256);
#pragma unroll
    for (int mt = 0; mt < 2; mt++) {
        int r0 = i0 + wi * 32 + mt * 16 + (lane >> 2);
#pragma unroll
        for (int nt = 0; nt < 8; nt++) {
            int col = j0 + wj * 64 + nt * 8 + (lane & 3) * 2;
            if (isT) {
                int c2 = col - 256;
                float b0 = bt1[c2], b1 = bt1[c2 + 1];
                if (r0 < M) {
                    Tf[(size_t)r0 * D + c2] = acc[mt][nt][0] + b0;
                    Tf[(size_t)r0 * D + c2 + 1] = acc[mt][nt][1] + b1;
                }
                int r1 = r0 + 8;
                if (r1 < M) {
                    Tf[(size_t)r1 * D + c2] = acc[mt][nt][2] + b0;
                    Tf[(size_t)r1 * D + c2 + 1] = acc[mt][nt][3] + b1;
                }
            } else {
                if (r0 < M) {
                    Xh[(size_t)r0 * D + col] = __float2bfloat16(acc[mt][nt][0]);
                    Xh[(size_t)r0 * D + col + 1] = __float2bfloat16(acc[mt][nt][1]);
                }
                int r1 = r0 + 8;
                if (r1 < M) {
                    Xh[(size_t)r1 * D + col] = __float2bfloat16(acc[mt][nt][2]);
                    Xh[(size_t)r1 * D + col + 1] = __float2bfloat16(acc[mt][nt][3]);
                }
            }
        }
    }
}

// ---------------- fused dual negsum (bf16 HMMA) ----------------
__global__ __launch_bounds__(256, 2) void negmma2_k(
    const __nv_bfloat16* __restrict__ Z, const __nv_bfloat16* __restrict__ Q,
    float* __restrict__ s1, float* __restrict__ s2, int n, int nJT) {
    extern __shared__ char dsm[];
    uint32_t aBase = (uint32_t)__cvta_generic_to_shared(dsm);        // 65536 B
    uint32_t bBase = aBase + 65536;                                   // 2 x 16384 B
    int tid = threadIdx.x;
    int lane = tid & 31, warp = tid >> 5;
    int wi = warp >> 1, wj = warp & 1;
    int i0 = blockIdx.x * 128;

    int a_row = (lane & 15);
    int a_chsel = (lane >> 4);
    int b_row = (lane & 7) + ((lane >> 4) & 1) * 8;
    int b_chsel = ((lane >> 3) & 1);

#pragma unroll
    for (int t = 0; t < 16; t++) {
        int c = tid + t * 256;
        int blk = c >> 10, idx = c & 1023;
        int row = idx >> 3, ch = idx & 7;
        uint32_t off = (uint32_t)(blk * 16384 + row * 128 + ((ch ^ (row & 7)) << 4));
        cp16(aBase + off, Z + (size_t)(i0 + row) * D + blk * 64 + ch * 8);
    }
    asm volatile("cp.async.commit_group;" ::: "memory");

    float rs[2][2][2];
#pragma unroll
    for (int a = 0; a < 2; a++)
#pragma unroll
        for (int b = 0; b < 2; b++)
#pragma unroll
            for (int c = 0; c < 2; c++) rs[a][b][c] = 0.f;

    for (int jt = blockIdx.y; jt < nJT; jt += gridDim.y) {
        int j0 = jt * 128;
#pragma unroll 1
        for (int sel = 0; sel < 2; sel++) {
            const __nv_bfloat16* Bg = (sel ? Q : Z) + (size_t)j0 * D;
            loadB64(bBase, Bg, 0, D, tid);
            float acc[2][8][4];
#pragma unroll
            for (int x = 0; x < 2; x++)
#pragma unroll
                for (int y = 0; y < 8; y++)
#pragma unroll
                    for (int v = 0; v < 4; v++) acc[x][y][v] = 0.f;

#pragma unroll
            for (int kt = 0; kt < 4; kt++) {
                asm volatile("cp.async.wait_group 0;" ::: "memory");
                __syncthreads();
                if (kt < 3) loadB64(bBase + ((kt + 1) & 1) * 16384, Bg, (kt + 1) * 64, D, tid);
                uint32_t sAu = aBase + kt * 16384;
                uint32_t sBu = bBase + (kt & 1) * 16384;
#pragma unroll
                for (int ks = 0; ks < 4; ks++) {
                    uint32_t afr[2][4];
#pragma unroll
                    for (int mt = 0; mt < 2; mt++) {
                        int row = wi * 32 + mt * 16 + a_row;
                        int ch = ks * 2 + a_chsel;
                        uint32_t addr = sAu + (uint32_t)(row * 128 + ((ch ^ (row & 7)) << 4));
                        ldsm4(addr, afr[mt][0], afr[mt][1], afr[mt][2], afr[mt][3]);
                    }
#pragma unroll
                    for (int p = 0; p < 4; p++) {
                        int nrow = wj * 64 + p * 16 + b_row;
                        int ch = ks * 2 + b_chsel;
                        uint32_t addr = sBu + (uint32_t)(nrow * 128 + ((ch ^ (nrow & 7)) << 4));
                        uint32_t bf0, bf1, bf2, bf3;
                        ldsm4(addr, bf0, bf1, bf2, bf3);
#pragma unroll
                        for (int mt = 0; mt < 2; mt++) {
                            mma16816(acc[mt][2 * p], afr[mt], bf0, bf1);
                            mma16816(acc[mt][2 * p + 1], afr[mt], bf2, bf3);
                        }
                    }
                }
                __syncthreads();
            }
#pragma unroll
            for (int mt = 0; mt < 2; mt++) {
#pragma unroll
                for (int nt = 0; nt < 8; nt++) {
                    int j = j0 + wj * 64 + nt * 8 + (lane & 3) * 2;
                    float e0 = (j < n) ? __expf(acc[mt][nt][0] * TEMP_INV) : 0.f;
                    float e1 = (j + 1 < n) ? __expf(acc[mt][nt][1] * TEMP_INV) : 0.f;
                    float e2 = (j < n) ? __expf(acc[mt][nt][2] * TEMP_INV) : 0.f;
                    float e3 = (j + 1 < n) ? __expf(acc[mt][nt][3] * TEMP_INV) : 0.f;
                    rs[sel][mt][0] += e0 + e1;
                    rs[sel][mt][1] += e2 + e3;
                }
            }
        }
    }
#pragma unroll
    for (int sel = 0; sel < 2; sel++) {
        float* out = sel ? s2 : s1;
#pragma unroll
        for (int mt = 0; mt < 2; mt++) {
#pragma unroll
            for (int h = 0; h < 2; h++) {
                float v = rs[sel][mt][h];
                v += __shfl_xor_sync(0xffffffffu, v, 1);
                v += __shfl_xor_sync(0xffffffffu, v, 2);
                if ((lane & 3) == 0) {
                    int i = i0 + wi * 32 + mt * 16 + h * 8 + (lane >> 2);
                    if (i < n) atomicAdd(&out[i], v);
                }
            }
        }
    }
}

// ------------------------------ launcher ------------------------------
static float* symf(const void* s) { void* p = nullptr; cudaGetSymbolAddress(&p, s); return (float*)p; }
static int* symi(const void* s) { void* p = nullptr; cudaGetSymbolAddress(&p, s); return (int*)p; }
static __nv_bfloat16* symh(const void* s) { void* p = nullptr; cudaGetSymbolAddress(&p, s); return (__nv_bfloat16*)p; }

extern "C" void kernel_launch(void* const* d_in, const int* in_sizes, int n_in,
                              void* d_out, int out_size) {
    const float* feat  = (const float*)d_in[0];
    const float* W1    = (const float*)d_in[1];
    const float* b1    = (const float*)d_in[2];
    const float* W2    = (const float*)d_in[3];
    const float* b2    = (const float*)d_in[4];
    const float* Wt1   = (const float*)d_in[5];
    const float* bt1   = (const float*)d_in[6];
    const float* gamma = (const float*)d_in[7];
    const float* beta  = (const float*)d_in[8];
    const float* Wt2   = (const float*)d_in[9];
    const float* bt2   = (const float*)d_in[10];
    const float* Wp    = (const float*)d_in[11];
    const float* bp    = (const float*)d_in[12];
    const int*   src   = (const int*)d_in[13];
    const int*   dst   = (const int*)d_in[14];

    const int IN = 512;
    int n = in_sizes[0] / IN;
    int e = in_sizes[13];
    int nTI = (n + 127) / 128;

    float* tbuf = symf(g_t);
    float* pbuf = symf(g_p);
    __nv_bfloat16* featb = symh(g_featb);
    __nv_bfloat16* xwb = symh(g_xwb);
    __nv_bfloat16* h1b = symh(g_h1b);
    __nv_bfloat16* tb = symh(g_tb);
    __nv_bfloat16* transb = symh(g_transb);
    __nv_bfloat16* zh = symh(g_zh);
    __nv_bfloat16* qh = symh(g_qh);
    __nv_bfloat16* Wcomb = symh(g_Wcomb);
    __nv_bfloat16* W2b = symh(g_W2b);
    __nv_bfloat16* Wt2b = symh(g_Wt2b);
    __nv_bfloat16* Wpb = symh(g_Wpb);
    float* dout = symf(g_degout);
    float* din  = symf(g_degin);
    float* rsd  = symf(g_rsd);
    int* cnt = symi(g_cnt);
    int* off = symi(g_off);
    int* cur = symi(g_cur);
    int* csrc = symi(g_csrc);
    float* musum = symf(g_musum);
    float* varsum = symf(g_varsum);
    float* s1 = symf(g_s1);
    float* s2 = symf(g_s2);
    float* pos = symf(g_pos);
    float* out = (float*)d_out;

    int nd = n * D;
    dim3 gemm_grid(nTI, 2);
    dim3 dual_grid(nTI, 4);
    int node_warp_blocks = (n * 32 + 255) / 256;

    static cudaStream_t sA = nullptr, sB = nullptr;
    static cudaEvent_t evStart, evCSR, evG1, evGCN, evQ, evPos;
    if (sA == nullptr) {
        cudaStreamCreateWithFlags(&sA, cudaStreamNonBlocking);
        cudaStreamCreateWithFlags(&sB, cudaStreamNonBlocking);
        cudaEventCreateWithFlags(&evStart, cudaEventDisableTiming);
        cudaEventCreateWithFlags(&evCSR, cudaEventDisableTiming);
        cudaEventCreateWithFlags(&evG1, cudaEventDisableTiming);
        cudaEventCreateWithFlags(&evGCN, cudaEventDisableTiming);
        cudaEventCreateWithFlags(&evQ, cudaEventDisableTiming);
        cudaEventCreateWithFlags(&evPos, cudaEventDisableTiming);
        cudaFuncSetAttribute(gemm_bf16_k, cudaFuncAttributeMaxDynamicSharedMemorySize, 2 * STAGE_BYTES);
        cudaFuncSetAttribute(gemm_dual_k, cudaFuncAttributeMaxDynamicSharedMemorySize, 2 * STAGE_BYTES);
        cudaFuncSetAttribute(negmma2_k, cudaFuncAttributeMaxDynamicSharedMemorySize, 98304);
    }

    // ---- fork CSR chain to sB ----
    cudaEventRecord(evStart, 0);
    cudaStreamWaitEvent(sB, evStart, 0);
    zero3_k<<<(n + 255) / 256, 256, 0, sB>>>(dout, din, cnt, n);
    degree_k<<<(e + 255) / 256, 256, 0, sB>>>(src, dst, dout, din, cnt, e);
    rsdcur_k<<<(n + 255) / 256, 256, 0, sB>>>(dout, rsd, cur, n);
    scan_k<<<1, 1024, 0, sB>>>(cnt, off, n);
    fillcsr_k<<<(e + 255) / 256, 256, 0, sB>>>(src, dst, off, cur, csrc, e);
    cudaEventRecord(evCSR, sB);

    // ---- main: conversions + dual first-layer gemm ----
    f2b_k<<<(n * IN + 255) / 256, 256>>>(feat, featb, n * IN);
    wconvall_k<<<(458752 + 255) / 256, 256>>>(W1, Wt1, W2, Wt2, Wp,
                                              Wcomb, Wcomb + 256 * 512, W2b, Wt2b, Wpb);
    gemm_dual_k<<<dual_grid, 256, 2 * STAGE_BYTES>>>(featb, Wcomb, bt1, xwb, tbuf, n, IN);
    cudaEventRecord(evG1, 0);

    // ---- fork GCN branch to sA ----
    cudaStreamWaitEvent(sA, evG1, 0);
    cudaStreamWaitEvent(sA, evCSR, 0);
    gather_agg_k<<<node_warp_blocks, 256, 0, sA>>>(xwb, csrc, off, rsd, din, b1, h1b, n, 1, 0);
    gemm_bf16_k<<<gemm_grid, 256, 2 * STAGE_BYTES, sA>>>(h1b, W2b, nullptr, nullptr, xwb, n, D, 0);
    gather_agg_k<<<node_warp_blocks, 256, 0, sA>>>(xwb, csrc, off, rsd, din, b2, zh, n, 0, 1);
    cudaEventRecord(evGCN, sA);

    // ---- main: target MLP branch ----
    zero2_k<<<1, 256>>>(musum, varsum, D);
    bnstat_k<<<100, 256>>>(tbuf, musum, varsum, n);
    bnapply_k<<<(nd + 255) / 256, 256>>>(tbuf, musum, varsum, gamma, beta, tb, n);
    gemm_bf16_k<<<gemm_grid, 256, 2 * STAGE_BYTES>>>(tb, Wt2b, bt2, nullptr, transb, n, D, 0);
    gemm_bf16_k<<<gemm_grid, 256, 2 * STAGE_BYTES>>>(transb, Wpb, bp, pbuf, nullptr, n, D, 0);
    norml1_k<<<(n * 32 + 255) / 256, 256>>>(pbuf, qh, n);
    cudaEventRecord(evQ, 0);
    zero2_k<<<(n + 255) / 256, 256>>>(s1, s2, n);
    zero_k<<<1, 32>>>(out, out_size);

    // ---- fork pos to sA (needs zh from sA program order + qh) ----
    cudaStreamWaitEvent(sA, evQ, 0);
    gather_pos_k<<<node_warp_blocks, 256, 0, sA>>>(zh, qh, csrc, off, pos, n);
    cudaEventRecord(evPos, sA);

    // ---- main: negsum (needs zh + qh) ----
    cudaStreamWaitEvent(0, evGCN, 0);
    dim3 neg_grid(nTI, 24);
    negmma2_k<<<neg_grid, 256, 98304>>>(zh, qh, s1, s2, n, nTI);

    // ---- join + fused mneg + loss ----
    cudaStreamWaitEvent(0, evPos, 0);
    mneg_loss_k<<<node_warp_blocks, 256>>>(s1, s2, pos, csrc, off, out, n);
}

// round 14
// speedup vs baseline: 1.3172x; 1.0950x over previous
#include <cuda_runtime.h>
#include <cuda_bf16.h>
#include <stdint.h>
#include <math.h>

#define NMAX 10240
#define EMAX 340000
#define D 256
#define INMAX 512
#define TEMP_INV 2.0f
#define LAM 1e-3f
#define BN_EPS 1e-5f

// ------------------------------ scratch (BSS zero-initialized) ------------------------------
__device__ __align__(16) float g_t[NMAX * D];
__device__ __align__(16) float g_p[NMAX * D];
__device__ __align__(16) __nv_bfloat16 g_featb[NMAX * INMAX];
__device__ __align__(16) __nv_bfloat16 g_xwb[NMAX * D];
__device__ __align__(16) __nv_bfloat16 g_h1b[NMAX * D];
__device__ __align__(16) __nv_bfloat16 g_tb[NMAX * D];
__device__ __align__(16) __nv_bfloat16 g_transb[NMAX * D];
__device__ __align__(16) __nv_bfloat16 g_zh[NMAX * D];
__device__ __align__(16) __nv_bfloat16 g_qh[NMAX * D];
__device__ __align__(16) __nv_bfloat16 g_Wcomb[INMAX * INMAX];  // rows 0-255 W1^T, 256-511 Wt1^T
__device__ __align__(16) __nv_bfloat16 g_W2b[D * D];
__device__ __align__(16) __nv_bfloat16 g_Wt2b[D * D];
__device__ __align__(16) __nv_bfloat16 g_Wpb[D * D];
__device__ float g_degout[NMAX];
__device__ float g_degin[NMAX];
__device__ float g_rsd[NMAX];
__device__ int   g_cnt[NMAX];
__device__ int   g_off[NMAX + 1];
__device__ int   g_cur[NMAX];
__device__ int   g_csrc[EMAX];
__device__ float g_musum[D];
__device__ float g_varsum[D];
__device__ float g_s1[NMAX];
__device__ float g_s2[NMAX];
__device__ float g_pos[NMAX];

// ------------------------------ small kernels ------------------------------
__global__ void zero2_k(float* a, float* b, int n) {
    int i = blockIdx.x * blockDim.x + threadIdx.x;
    if (i < n) { a[i] = 0.f; b[i] = 0.f; }
}
__global__ void zero3_k(float* a, float* b, int* c, int n) {
    int i = blockIdx.x * blockDim.x + threadIdx.x;
    if (i < n) { a[i] = 0.f; b[i] = 0.f; c[i] = 0; }
}
__global__ void zero_k(float* p, int n) {
    int i = blockIdx.x * blockDim.x + threadIdx.x;
    if (i < n) p[i] = 0.f;
}

__global__ void f2b_k(const float* __restrict__ x, __nv_bfloat16* __restrict__ y, int n) {
    int i = blockIdx.x * blockDim.x + threadIdx.x;
    if (i < n) y[i] = __float2bfloat16(x[i]);
}

__global__ void wconvall_k(const float* W1, const float* Wt1,
                           const float* W2, const float* Wt2, const float* Wp,
                           __nv_bfloat16* W1c, __nv_bfloat16* Wt1c,
                           __nv_bfloat16* W2b, __nv_bfloat16* Wt2b,
                           __nv_bfloat16* Wpb) {
    int i = blockIdx.x * blockDim.x + threadIdx.x;
    const float* W; __nv_bfloat16* O; int K, li;
    if (i < 131072)        { W = W1;  O = W1c;  K = 512; li = i; }
    else if (i < 262144)   { W = Wt1; O = Wt1c; K = 512; li = i - 131072; }
    else if (i < 327680)   { W = W2;  O = W2b;  K = 256; li = i - 262144; }
    else if (i < 393216)   { W = Wt2; O = Wt2b; K = 256; li = i - 327680; }
    else if (i < 458752)   { W = Wp;  O = Wpb;  K = 256; li = i - 393216; }
    else return;
    int k = li >> 8, n = li & 255;
    O[n * K + k] = __float2bfloat16(W[(size_t)k * 256 + n]);
}

__global__ void degree_k(const int* __restrict__ src, const int* __restrict__ dst,
                         float* dout, float* din, int* cnt, int e) {
    int i = blockIdx.x * blockDim.x + threadIdx.x;
    if (i < e) {
        atomicAdd(&dout[src[i]], 1.f);
        atomicAdd(&din[dst[i]], 1.f);
        atomicAdd(&cnt[dst[i]], 1);
    }
}

__global__ void rsdcur_k(const float* __restrict__ dout, float* rsd, int* cur, int n) {
    int i = blockIdx.x * blockDim.x + threadIdx.x;
    if (i < n) { rsd[i] = rsqrtf(dout[i]); cur[i] = 0; }
}

__global__ void scan_k(const int* __restrict__ cnt, int* off, int n) {
    __shared__ int ts[1024];
    int t = threadIdx.x;
    int L = (n + 1023) >> 10;
    int b = t * L, eidx = min(b + L, n);
    int s = 0;
    for (int i = b; i < eidx; i++) s += cnt[i];
    ts[t] = s;
    __syncthreads();
    for (int d2 = 1; d2 < 1024; d2 <<= 1) {
        int v = (t >= d2) ? ts[t - d2] : 0;
        __syncthreads();
        ts[t] += v;
        __syncthreads();
    }
    int base = (t == 0) ? 0 : ts[t - 1];
    for (int i = b; i < eidx; i++) { off[i] = base; base += cnt[i]; }
    if (t == 1023) off[n] = ts[1023];
}

__global__ void fillcsr_k(const int* __restrict__ src, const int* __restrict__ dst,
                          const int* __restrict__ off, int* cur, int* csrc, int e) {
    int i = blockIdx.x * blockDim.x + threadIdx.x;
    if (i < e) {
        int d = dst[i];
        int p = off[d] + atomicAdd(&cur[d], 1);
        csrc[p] = src[i];
    }
}

// gather agg, one warp per dst node, unroll-8; optional fused L2-normalize
__global__ void gather_agg_k(const __nv_bfloat16* __restrict__ xw,
                             const int* __restrict__ csrc, const int* __restrict__ off,
                             const float* __restrict__ rsd, const float* __restrict__ din,
                             const float* __restrict__ bias,
                             __nv_bfloat16* outh, int n, int relu, int norm) {
    int d = (blockIdx.x * blockDim.x + threadIdx.x) >> 5;
    int lane = threadIdx.x & 31;
    if (d >= n) return;
    float acc[8] = {};
    int p0 = off[d], p1 = off[d + 1];
    int p = p0;
    for (; p + 8 <= p1; p += 8) {
        int si[8];
#pragma unroll
        for (int u = 0; u < 8; u++) si[u] = __ldg(csrc + p + u);
        uint4 v[8];
#pragma unroll
        for (int u = 0; u < 8; u++) v[u] = *((const uint4*)(xw + (size_t)si[u] * D) + lane);
        float w[8];
#pragma unroll
        for (int u = 0; u < 8; u++) w[u] = rsd[si[u]];
#pragma unroll
        for (int u = 0; u < 8; u++) {
            const __nv_bfloat16* hv = (const __nv_bfloat16*)&v[u];
#pragma unroll
            for (int k = 0; k < 8; k++) acc[k] += __bfloat162float(hv[k]) * w[u];
        }
    }
    for (; p < p1; p++) {
        int s = __ldg(csrc + p);
        float w = rsd[s];
        uint4 vv = *((const uint4*)(xw + (size_t)s * D) + lane);
        const __nv_bfloat16* hv = (const __nv_bfloat16*)&vv;
#pragma unroll
        for (int k = 0; k < 8; k++) acc[k] += __bfloat162float(hv[k]) * w;
    }
    float sc = rsqrtf(din[d]);
    int col = lane * 8;
    float o[8];
#pragma unroll
    for (int k = 0; k < 8; k++) {
        float v = acc[k] * sc + bias[col + k];
        o[k] = relu ? fmaxf(v, 0.f) : v;
    }
    if (norm) {
        float ss = 0.f;
#pragma unroll
        for (int k = 0; k < 8; k++) ss += o[k] * o[k];
#pragma unroll
        for (int os = 16; os > 0; os >>= 1) ss += __shfl_xor_sync(0xffffffffu, ss, os);
        float inv = 1.f / fmaxf(sqrtf(ss), 1e-12f);
#pragma unroll
        for (int k = 0; k < 8; k++) o[k] *= inv;
    }
    __nv_bfloat16 hb[8];
#pragma unroll
    for (int k = 0; k < 8; k++) hb[k] = __float2bfloat16(o[k]);
    *(uint4*)(outh + (size_t)d * D + col) = *(uint4*)hb;
}

__global__ void bnstat_k(const float* __restrict__ t, float* musum, float* varsum, int M) {
    int col = threadIdx.x;
    int rpb = (M + gridDim.x - 1) / gridDim.x;
    int r0 = blockIdx.x * rpb;
    int r1 = min(r0 + rpb, M);
    float s = 0.f, s2 = 0.f;
    for (int r = r0; r < r1; r++) {
        float v = t[(size_t)r * D + col];
        s += v; s2 += v * v;
    }
    atomicAdd(&musum[col], s);
    atomicAdd(&varsum[col], s2);
}

__global__ void bnapply_k(const float* __restrict__ t, const float* __restrict__ musum,
                          const float* __restrict__ varsum,
                          const float* __restrict__ gamma, const float* __restrict__ beta,
                          __nv_bfloat16* th, int M) {
    int i = blockIdx.x * blockDim.x + threadIdx.x;
    if (i < M * D) {
        int c = i & (D - 1);
        float mu = musum[c] / M;
        float var = varsum[c] / M - mu * mu;
        float v = (t[i] - mu) * rsqrtf(var + BN_EPS) * gamma[c] + beta[c];
        th[i] = __float2bfloat16(fmaxf(v, 0.f));
    }
}

__global__ void norml1_k(const float* __restrict__ x, __nv_bfloat16* __restrict__ zh, int M) {
    int row = (blockIdx.x * blockDim.x + threadIdx.x) >> 5;
    int lane = threadIdx.x & 31;
    if (row >= M) return;
    const float* xr = x + (size_t)row * D;
    float s = 0.f;
#pragma unroll
    for (int c = 0; c < D / 32; c++) {
        float v = xr[lane + 32 * c];
        s += v * v;
    }
#pragma unroll
    for (int o = 16; o > 0; o >>= 1) s += __shfl_xor_sync(0xffffffffu, s, o);
    float inv = 1.f / fmaxf(sqrtf(s), 1e-12f);
    __nv_bfloat16* hr = zh + (size_t)row * D;
#pragma unroll
    for (int c = 0; c < D / 32; c++) {
        int f = lane + 32 * c;
        hr[f] = __float2bfloat16(xr[f] * inv);
    }
}

__global__ void gather_pos_k(const __nv_bfloat16* __restrict__ zh,
                             const __nv_bfloat16* __restrict__ qh,
                             const int* __restrict__ csrc, const int* __restrict__ off,
                             float* pos, int n) {
    int d = (blockIdx.x * blockDim.x + threadIdx.x) >> 5;
    int lane = threadIdx.x & 31;
    if (d >= n) return;
    uint4 qv = *((const uint4*)(qh + (size_t)d * D) + lane);
    const __nv_bfloat16* qe = (const __nv_bfloat16*)&qv;
    float qf[8];
#pragma unroll
    for (int k = 0; k < 8; k++) qf[k] = __bfloat162float(qe[k]);
    float sz[8] = {};
    int p0 = off[d], p1 = off[d + 1];
    int p = p0;
    for (; p + 8 <= p1; p += 8) {
        int si[8];
#pragma unroll
        for (int u = 0; u < 8; u++) si[u] = __ldg(csrc + p + u);
        uint4 v[8];
#pragma unroll
        for (int u = 0; u < 8; u++) v[u] = *((const uint4*)(zh + (size_t)si[u] * D) + lane);
#pragma unroll
        for (int u = 0; u < 8; u++) {
            const __nv_bfloat16* hv = (const __nv_bfloat16*)&v[u];
#pragma unroll
            for (int k = 0; k < 8; k++) sz[k] += __bfloat162float(hv[k]);
        }
    }
    for (; p < p1; p++) {
        int s = __ldg(csrc + p);
        uint4 vv = *((const uint4*)(zh + (size_t)s * D) + lane);
        const __nv_bfloat16* hv = (const __nv_bfloat16*)&vv;
#pragma unroll
        for (int k = 0; k < 8; k++) sz[k] += __bfloat162float(hv[k]);
    }
    float dot = 0.f;
#pragma unroll
    for (int k = 0; k < 8; k++) dot += sz[k] * qf[k];
#pragma unroll
    for (int o = 16; o > 0; o >>= 1) dot += __shfl_xor_sync(0xffffffffu, dot, o);
    if (lane == 0) pos[d] = dot * TEMP_INV;
}

__global__ void mneg_loss_k(const float* __restrict__ s1, const float* __restrict__ s2,
                            const float* __restrict__ pos,
                            const int* __restrict__ csrc, const int* __restrict__ off,
                            float* out, int n) {
    __shared__ float ws[8];
    int tid = threadIdx.x;
    int lane = tid & 31, warp = tid >> 5;
    int d = (blockIdx.x * blockDim.x + tid) >> 5;
    float contrib = 0.f;
    if (d < n) {
        float base = s1[d];
        float acc = 0.f;
        int p0 = off[d], p1 = off[d + 1];
        for (int p = p0 + lane; p < p1; p += 32)
            acc += __logf(base + LAM * s2[__ldg(csrc + p)]);
#pragma unroll
        for (int o = 16; o > 0; o >>= 1) acc += __shfl_xor_sync(0xffffffffu, acc, o);
        if (lane == 0) contrib = (acc - pos[d]) / (float)(p1 - p0);
    }
    if (lane == 0) ws[warp] = contrib;
    __syncthreads();
    if (tid == 0) {
        float t = 0.f;
#pragma unroll
        for (int w = 0; w < 8; w++) t += ws[w];
        atomicAdd(out, t / n);
    }
}

// ---------------- mma helpers ----------------
__device__ __forceinline__ void ldsm4(uint32_t addr, uint32_t& r0, uint32_t& r1,
                                      uint32_t& r2, uint32_t& r3) {
    asm volatile("ldmatrix.sync.aligned.m8n8.x4.shared.b16 {%0,%1,%2,%3}, [%4];"
                 : "=r"(r0), "=r"(r1), "=r"(r2), "=r"(r3) : "r"(addr));
}
__device__ __forceinline__ void mma16816(float* c, const uint32_t* a,
                                         uint32_t b0, uint32_t b1) {
    asm volatile(
        "mma.sync.aligned.m16n8k16.row.col.f32.bf16.bf16.f32 "
        "{%0,%1,%2,%3}, {%4,%5,%6,%7}, {%8,%9}, {%0,%1,%2,%3};"
        : "+f"(c[0]), "+f"(c[1]), "+f"(c[2]), "+f"(c[3])
        : "r"(a[0]), "r"(a[1]), "r"(a[2]), "r"(a[3]), "r"(b0), "r"(b1));
}
__device__ __forceinline__ void cp16(uint32_t saddr, const void* g) {
    asm volatile("cp.async.cg.shared.global [%0], [%1], 16;"
                 :: "r"(saddr), "l"(g) : "memory");
}
__device__ __forceinline__ void loadB64(uint32_t sdst, const __nv_bfloat16* Bg,
                                        int k0, int ldb, int tid) {
#pragma unroll
    for (int t = 0; t < 4; t++) {
        int c = tid + t * 256;
        int row = c >> 3, ch = c & 7;
        uint32_t off = (uint32_t)(row * 128 + ((ch ^ (row & 7)) << 4));
        cp16(sdst + off, Bg + (size_t)row * ldb + k0 + ch * 8);
    }
    asm volatile("cp.async.commit_group;" ::: "memory");
}

#define STAGE_BYTES 32768

#define GEMM_MAINLOOP(A_, B_, K_)                                                     \
    int KT = (K_) >> 6;                                                               \
    loadB64(sbase, (A_), 0, (K_), tid);                                               \
    loadB64(sbase + 16384, (B_), 0, (K_), tid);                                       \
    for (int kt = 0; kt < KT; kt++) {                                                 \
        asm volatile("cp.async.wait_group 0;" ::: "memory");                          \
        __syncthreads();                                                              \
        if (kt + 1 < KT) {                                                            \
            uint32_t sa = sbase + ((kt + 1) & 1) * STAGE_BYTES;                       \
            loadB64(sa, (A_), (kt + 1) * 64, (K_), tid);                              \
            loadB64(sa + 16384, (B_), (kt + 1) * 64, (K_), tid);                      \
        }                                                                             \
        uint32_t sAu = sbase + (kt & 1) * STAGE_BYTES;                                \
        uint32_t sBu = sAu + 16384;                                                   \
        _Pragma("unroll")                                                             \
        for (int ks = 0; ks < 4; ks++) {                                              \
            uint32_t afr[2][4];                                                       \
            _Pragma("unroll")                                                         \
            for (int mt = 0; mt < 2; mt++) {                                          \
                int row = wi * 32 + mt * 16 + a_row;                                  \
                int ch = ks * 2 + a_chsel;                                            \
                uint32_t addr = sAu + (uint32_t)(row * 128 + ((ch ^ (row & 7)) << 4));\
                ldsm4(addr, afr[mt][0], afr[mt][1], afr[mt][2], afr[mt][3]);          \
            }                                                                         \
            _Pragma("unroll")                                                         \
            for (int pp = 0; pp < 4; pp++) {                                          \
                int nrow = wj * 64 + pp * 16 + b_row;                                 \
                int ch = ks * 2 + b_chsel;                                            \
                uint32_t addr = sBu + (uint32_t)(nrow * 128 + ((ch ^ (nrow & 7)) << 4));\
                uint32_t bf0, bf1, bf2, bf3;                                          \
                ldsm4(addr, bf0, bf1, bf2, bf3);                                      \
                _Pragma("unroll")                                                     \
                for (int mt = 0; mt < 2; mt++) {                                      \
                    mma16816(acc[mt][2 * pp], afr[mt], bf0, bf1);                     \
                    mma16816(acc[mt][2 * pp + 1], afr[mt], bf2, bf3);                 \
                }                                                                     \
            }                                                                         \
        }                                                                             \
        __syncthreads();                                                              \
    }

// ---------------- bf16 tensor GEMM: C = A[Mpad,K] @ Wt[256,K]^T ----------------
__global__ __launch_bounds__(256, 2) void gemm_bf16_k(
    const __nv_bfloat16* __restrict__ A, const __nv_bfloat16* __restrict__ Wt,
    const float* __restrict__ bias, float* __restrict__ Cf,
    __nv_bfloat16* __restrict__ Ch, int M, int K, int relu) {
    extern __shared__ char dsm[];
    uint32_t sbase = (uint32_t)__cvta_generic_to_shared(dsm);
    int tid = threadIdx.x;
    int lane = tid & 31, warp = tid >> 5;
    int wi = warp >> 1, wj = warp & 1;
    int i0 = blockIdx.x * 128, j0 = blockIdx.y * 128;

    int a_row = (lane & 15);
    int a_chsel = (lane >> 4);
    int b_row = (lane & 7) + ((lane >> 4) & 1) * 8;
    int b_chsel = ((lane >> 3) & 1);

    const __nv_bfloat16* Ag = A + (size_t)i0 * K;
    const __nv_bfloat16* Bg = Wt + (size_t)j0 * K;

    float acc[2][8][4];
#pragma unroll
    for (int x = 0; x < 2; x++)
#pragma unroll
        for (int y = 0; y < 8; y++)
#pragma unroll
            for (int v = 0; v < 4; v++) acc[x][y][v] = 0.f;

    GEMM_MAINLOOP(Ag, Bg, K)

#pragma unroll
    for (int mt = 0; mt < 2; mt++) {
        int r0 = i0 + wi * 32 + mt * 16 + (lane >> 2);
#pragma unroll
        for (int nt = 0; nt < 8; nt++) {
            int col = j0 + wj * 64 + nt * 8 + (lane & 3) * 2;
            float b0 = bias ? bias[col] : 0.f;
            float b1 = bias ? bias[col + 1] : 0.f;
            float v0 = acc[mt][nt][0] + b0, v1 = acc[mt][nt][1] + b1;
            float v2 = acc[mt][nt][2] + b0, v3 = acc[mt][nt][3] + b1;
            if (relu) {
                v0 = fmaxf(v0, 0.f); v1 = fmaxf(v1, 0.f);
                v2 = fmaxf(v2, 0.f); v3 = fmaxf(v3, 0.f);
            }
            if (r0 < M) {
                if (Cf) { Cf[(size_t)r0 * D + col] = v0; Cf[(size_t)r0 * D + col + 1] = v1; }
                if (Ch) {
                    Ch[(size_t)r0 * D + col] = __float2bfloat16(v0);
                    Ch[(size_t)r0 * D + col + 1] = __float2bfloat16(v1);
                }
            }
            int r1 = r0 + 8;
            if (r1 < M) {
                if (Cf) { Cf[(size_t)r1 * D + col] = v2; Cf[(size_t)r1 * D + col + 1] = v3; }
                if (Ch) {
                    Ch[(size_t)r1 * D + col] = __float2bfloat16(v2);
                    Ch[(size_t)r1 * D + col + 1] = __float2bfloat16(v3);
                }
            }
        }
    }
}

// ---------------- dual-output gemm: featb @ Wcomb[512,512]^T ----------------
__global__ __launch_bounds__(256, 2) void gemm_dual_k(
    const __nv_bfloat16* __restrict__ A, const __nv_bfloat16* __restrict__ Wc,
    const float* __restrict__ bt1, __nv_bfloat16* __restrict__ Xh,
    float* __restrict__ Tf, int M, int K) {
    extern __shared__ char dsm[];
    uint32_t sbase = (uint32_t)__cvta_generic_to_shared(dsm);
    int tid = threadIdx.x;
    int lane = tid & 31, warp = tid >> 5;
    int wi = warp >> 1, wj = warp & 1;
    int i0 = blockIdx.x * 128, j0 = blockIdx.y * 128;

    int a_row = (lane & 15);
    int a_chsel = (lane >> 4);
    int b_row = (lane & 7) + ((lane >> 4) & 1) * 8;
    int b_chsel = ((lane >> 3) & 1);

    const __nv_bfloat16* Ag = A + (size_t)i0 * K;
    const __nv_bfloat16* Bg = Wc + (size_t)j0 * K;

    float acc[2][8][4];
#pragma unroll
    for (int x = 0; x < 2; x++)
#pragma unroll
        for (int y = 0; y < 8; y++)
#pragma unroll
            for (int v = 0; v < 4; v++) acc[x][y][v] = 0.f;

    GEMM_MAINLOOP(Ag, Bg, K)

    int isT = (j0 >= 256);
#pragma unroll
    for (int mt = 0; mt < 2; mt++) {
        int r0 = i0 + wi * 32 + mt * 16 + (lane >> 2);
#pragma unroll
        for (int nt = 0; nt < 8; nt++) {
            int col = j0 + wj * 64 + nt * 8 + (lane & 3) * 2;
            if (isT) {
                int c2 = col - 256;
                float b0 = bt1[c2], b1 = bt1[c2 + 1];
                if (r0 < M) {
                    Tf[(size_t)r0 * D + c2] = acc[mt][nt][0] + b0;
                    Tf[(size_t)r0 * D + c2 + 1] = acc[mt][nt][1] + b1;
                }
                int r1 = r0 + 8;
                if (r1 < M) {
                    Tf[(size_t)r1 * D + c2] = acc[mt][nt][2] + b0;
                    Tf[(size_t)r1 * D + c2 + 1] = acc[mt][nt][3] + b1;
                }
            } else {
                if (r0 < M) {
                    Xh[(size_t)r0 * D + col] = __float2bfloat16(acc[mt][nt][0]);
                    Xh[(size_t)r0 * D + col + 1] = __float2bfloat16(acc[mt][nt][1]);
                }
                int r1 = r0 + 8;
                if (r1 < M) {
                    Xh[(size_t)r1 * D + col] = __float2bfloat16(acc[mt][nt][2]);
                    Xh[(size_t)r1 * D + col + 1] = __float2bfloat16(acc[mt][nt][3]);
                }
            }
        }
    }
}

// ---------------- symmetric fused dual negsum ----------------
// s1: z@z symmetric -> upper-triangle tiles only; row sums (regs) + col sums (smem->atomic)
// s2: z@q full tiles. A tile resident; B double-buffered per tile.
#define NEG_SMEM (98304 + 512)

__global__ __launch_bounds__(256, 2) void negsym_k(
    const __nv_bfloat16* __restrict__ Z, const __nv_bfloat16* __restrict__ Q,
    float* __restrict__ s1, float* __restrict__ s2, int n, int nTI) {
    extern __shared__ char dsm[];
    uint32_t aBase = (uint32_t)__cvta_generic_to_shared(dsm);        // 64 KB
    uint32_t bBase = aBase + 65536;                                   // 2 x 16 KB
    float* colsm = (float*)(dsm + 98304);                             // 128 floats
    int tid = threadIdx.x;
    int lane = tid & 31, warp = tid >> 5;
    int wi = warp >> 1, wj = warp & 1;
    int it = blockIdx.x;
    int i0 = it * 128;
    int gy = gridDim.y, by = blockIdx.y;

    int a_row = (lane & 15);
    int a_chsel = (lane >> 4);
    int b_row = (lane & 7) + ((lane >> 4) & 1) * 8;
    int b_chsel = ((lane >> 3) & 1);

    // resident A
#pragma unroll
    for (int t = 0; t < 16; t++) {
        int c = tid + t * 256;
        int blk = c >> 10, idx = c & 1023;
        int row = idx >> 3, ch = idx & 7;
        uint32_t off = (uint32_t)(blk * 16384 + row * 128 + ((ch ^ (row & 7)) << 4));
        cp16(aBase + off, Z + (size_t)(i0 + row) * D + blk * 64 + ch * 8);
    }
    asm volatile("cp.async.commit_group;" ::: "memory");

    float rs[2][2][2];
#pragma unroll
    for (int a = 0; a < 2; a++)
#pragma unroll
        for (int b = 0; b < 2; b++)
#pragma unroll
            for (int c = 0; c < 2; c++) rs[a][b][c] = 0.f;

    // row-validity for colsum masking (rows of A tile)
    // r(mt, half) = i0 + wi*32 + mt*16 + (lane>>2) + half*8
    int rbase = i0 + wi * 32 + (lane >> 2);
    float rv[2][2];
#pragma unroll
    for (int mt = 0; mt < 2; mt++) {
        rv[mt][0] = (rbase + mt * 16 < n) ? 1.f : 0.f;
        rv[mt][1] = (rbase + mt * 16 + 8 < n) ? 1.f : 0.f;
    }

#pragma unroll 1
    for (int sel = 0; sel < 2; sel++) {
        int jt0 = sel ? by : (it + by);
#pragma unroll 1
        for (int jt = jt0; jt < nTI; jt += gy) {
            int j0 = jt * 128;
            const __nv_bfloat16* Bg = (sel ? Q : Z) + (size_t)j0 * D;
            loadB64(bBase, Bg, 0, D, tid);
            float acc[2][8][4];
#pragma unroll
            for (int x = 0; x < 2; x++)
#pragma unroll
                for (int y = 0; y < 8; y++)
#pragma unroll
                    for (int v = 0; v < 4; v++) acc[x][y][v] = 0.f;

#pragma unroll
            for (int kt = 0; kt < 4; kt++) {
                asm volatile("cp.async.wait_group 0;" ::: "memory");
                __syncthreads();
                if (kt < 3) loadB64(bBase + ((kt + 1) & 1) * 16384, Bg, (kt + 1) * 64, D, tid);
                uint32_t sAu = aBase + kt * 16384;
                uint32_t sBu = bBase + (kt & 1) * 16384;
#pragma unroll
                for (int ks = 0; ks < 4; ks++) {
                    uint32_t afr[2][4];
#pragma unroll
                    for (int mt = 0; mt < 2; mt++) {
                        int row = wi * 32 + mt * 16 + a_row;
                        int ch = ks * 2 + a_chsel;
                        uint32_t addr = sAu + (uint32_t)(row * 128 + ((ch ^ (row & 7)) << 4));
                        ldsm4(addr, afr[mt][0], afr[mt][1], afr[mt][2], afr[mt][3]);
                    }
#pragma unroll
                    for (int p = 0; p < 4; p++) {
                        int nrow = wj * 64 + p * 16 + b_row;
                        int ch = ks * 2 + b_chsel;
                        uint32_t addr = sBu + (uint32_t)(nrow * 128 + ((ch ^ (nrow & 7)) << 4));
                        uint32_t bf0, bf1, bf2, bf3;
                        ldsm4(addr, bf0, bf1, bf2, bf3);
#pragma unroll
                        for (int mt = 0; mt < 2; mt++) {
                            mma16816(acc[mt][2 * p], afr[mt], bf0, bf1);
                            mma16816(acc[mt][2 * p + 1], afr[mt], bf2, bf3);
                        }
                    }
                }
                __syncthreads();
            }
            // epilogue: exp, rowsum (col-masked); for off-diag z@z tiles also colsum
            int doCol = (sel == 0) && (jt != it);
            if (doCol) {
                if (tid < 128) colsm[tid] = 0.f;
                __syncthreads();
            }
            float cs[8][2];
#pragma unroll
            for (int mt = 0; mt < 2; mt++) {
#pragma unroll
                for (int nt = 0; nt < 8; nt++) {
                    int j = j0 + wj * 64 + nt * 8 + (lane & 3) * 2;
                    float e0 = (j < n) ? __expf(acc[mt][nt][0] * TEMP_INV) : 0.f;
                    float e1 = (j + 1 < n) ? __expf(acc[mt][nt][1] * TEMP_INV) : 0.f;
                    float e2 = (j < n) ? __expf(acc[mt][nt][2] * TEMP_INV) : 0.f;
                    float e3 = (j + 1 < n) ? __expf(acc[mt][nt][3] * TEMP_INV) : 0.f;
                    rs[sel][mt][0] += e0 + e1;
                    rs[sel][mt][1] += e2 + e3;
                    if (doCol) {
                        float c0 = e0 * rv[mt][0] + e2 * rv[mt][1];
                        float c1 = e1 * rv[mt][0] + e3 * rv[mt][1];
                        if (mt == 0) { cs[nt][0] = c0; cs[nt][1] = c1; }
                        else { cs[nt][0] += c0; cs[nt][1] += c1; }
                    }
                }
            }
            if (doCol) {
                // reduce over lane>>2 (rows) via xor shuffles
#pragma unroll
                for (int nt = 0; nt < 8; nt++) {
#pragma unroll
                    for (int h = 0; h < 2; h++) {
                        float v = cs[nt][h];
                        v += __shfl_xor_sync(0xffffffffu, v, 4);
                        v += __shfl_xor_sync(0xffffffffu, v, 8);
                        v += __shfl_xor_sync(0xffffffffu, v, 16);
                        cs[nt][h] = v;
                    }
                }
                if (lane < 4) {
#pragma unroll
                    for (int nt = 0; nt < 8; nt++) {
                        int cc = wj * 64 + nt * 8 + lane * 2;
                        atomicAdd(&colsm[cc], cs[nt][0]);
                        atomicAdd(&colsm[cc + 1], cs[nt][1]);
                    }
                }
                __syncthreads();
                if (tid < 128) {
                    int j = j0 + tid;
                    if (j < n) atomicAdd(&s1[j], colsm[tid]);
                }
                __syncthreads();
            }
        }
    }
#pragma unroll
    for (int sel = 0; sel < 2; sel++) {
        float* out = sel ? s2 : s1;
#pragma unroll
        for (int mt = 0; mt < 2; mt++) {
#pragma unroll
            for (int h = 0; h < 2; h++) {
                float v = rs[sel][mt][h];
                v += __shfl_xor_sync(0xffffffffu, v, 1);
                v += __shfl_xor_sync(0xffffffffu, v, 2);
                if ((lane & 3) == 0) {
                    int i = i0 + wi * 32 + mt * 16 + h * 8 + (lane >> 2);
                    if (i < n) atomicAdd(&out[i], v);
                }
            }
        }
    }
}

// ------------------------------ launcher ------------------------------
static float* symf(const void* s) { void* p = nullptr; cudaGetSymbolAddress(&p, s); return (float*)p; }
static int* symi(const void* s) { void* p = nullptr; cudaGetSymbolAddress(&p, s); return (int*)p; }
static __nv_bfloat16* symh(const void* s) { void* p = nullptr; cudaGetSymbolAddress(&p, s); return (__nv_bfloat16*)p; }

extern "C" void kernel_launch(void* const* d_in, const int* in_sizes, int n_in,
                              void* d_out, int out_size) {
    const float* feat  = (const float*)d_in[0];
    const float* W1    = (const float*)d_in[1];
    const float* b1    = (const float*)d_in[2];
    const float* W2    = (const float*)d_in[3];
    const float* b2    = (const float*)d_in[4];
    const float* Wt1   = (const float*)d_in[5];
    const float* bt1   = (const float*)d_in[6];
    const float* gamma = (const float*)d_in[7];
    const float* beta  = (const float*)d_in[8];
    const float* Wt2   = (const float*)d_in[9];
    const float* bt2   = (const float*)d_in[10];
    const float* Wp    = (const float*)d_in[11];
    const float* bp    = (const float*)d_in[12];
    const int*   src   = (const int*)d_in[13];
    const int*   dst   = (const int*)d_in[14];

    const int IN = 512;
    int n = in_sizes[0] / IN;
    int e = in_sizes[13];
    int nTI = (n + 127) / 128;

    float* tbuf = symf(g_t);
    float* pbuf = symf(g_p);
    __nv_bfloat16* featb = symh(g_featb);
    __nv_bfloat16* xwb = symh(g_xwb);
    __nv_bfloat16* h1b = symh(g_h1b);
    __nv_bfloat16* tb = symh(g_tb);
    __nv_bfloat16* transb = symh(g_transb);
    __nv_bfloat16* zh = symh(g_zh);
    __nv_bfloat16* qh = symh(g_qh);
    __nv_bfloat16* Wcomb = symh(g_Wcomb);
    __nv_bfloat16* W2b = symh(g_W2b);
    __nv_bfloat16* Wt2b = symh(g_Wt2b);
    __nv_bfloat16* Wpb = symh(g_Wpb);
    float* dout = symf(g_degout);
    float* din  = symf(g_degin);
    float* rsd  = symf(g_rsd);
    int* cnt = symi(g_cnt);
    int* off = symi(g_off);
    int* cur = symi(g_cur);
    int* csrc = symi(g_csrc);
    float* musum = symf(g_musum);
    float* varsum = symf(g_varsum);
    float* s1 = symf(g_s1);
    float* s2 = symf(g_s2);
    float* pos = symf(g_pos);
    float* out = (float*)d_out;

    int nd = n * D;
    dim3 gemm_grid(nTI, 2);
    dim3 dual_grid(nTI, 4);
    int node_warp_blocks = (n * 32 + 255) / 256;

    static cudaStream_t sA = nullptr, sB = nullptr;
    static cudaEvent_t evStart, evCSR, evG1, evGCN, evQ, evPos;
    if (sA == nullptr) {
        cudaStreamCreateWithFlags(&sA, cudaStreamNonBlocking);
        cudaStreamCreateWithFlags(&sB, cudaStreamNonBlocking);
        cudaEventCreateWithFlags(&evStart, cudaEventDisableTiming);
        cudaEventCreateWithFlags(&evCSR, cudaEventDisableTiming);
        cudaEventCreateWithFlags(&evG1, cudaEventDisableTiming);
        cudaEventCreateWithFlags(&evGCN, cudaEventDisableTiming);
        cudaEventCreateWithFlags(&evQ, cudaEventDisableTiming);
        cudaEventCreateWithFlags(&evPos, cudaEventDisableTiming);
        cudaFuncSetAttribute(gemm_bf16_k, cudaFuncAttributeMaxDynamicSharedMemorySize, 2 * STAGE_BYTES);
        cudaFuncSetAttribute(gemm_dual_k, cudaFuncAttributeMaxDynamicSharedMemorySize, 2 * STAGE_BYTES);
        cudaFuncSetAttribute(negsym_k, cudaFuncAttributeMaxDynamicSharedMemorySize, NEG_SMEM);
    }

    // ---- fork CSR chain to sB ----
    cudaEventRecord(evStart, 0);
    cudaStreamWaitEvent(sB, evStart, 0);
    zero3_k<<<(n + 255) / 256, 256, 0, sB>>>(dout, din, cnt, n);
    degree_k<<<(e + 255) / 256, 256, 0, sB>>>(src, dst, dout, din, cnt, e);
    rsdcur_k<<<(n + 255) / 256, 256, 0, sB>>>(dout, rsd, cur, n);
    scan_k<<<1, 1024, 0, sB>>>(cnt, off, n);
    fillcsr_k<<<(e + 255) / 256, 256, 0, sB>>>(src, dst, off, cur, csrc, e);
    cudaEventRecord(evCSR, sB);

    // ---- main: conversions + dual first-layer gemm ----
    f2b_k<<<(n * IN + 255) / 256, 256>>>(feat, featb, n * IN);
    wconvall_k<<<(458752 + 255) / 256, 256>>>(W1, Wt1, W2, Wt2, Wp,
                                              Wcomb, Wcomb + 256 * 512, W2b, Wt2b, Wpb);
    gemm_dual_k<<<dual_grid, 256, 2 * STAGE_BYTES>>>(featb, Wcomb, bt1, xwb, tbuf, n, IN);
    cudaEventRecord(evG1, 0);

    // ---- fork GCN branch to sA ----
    cudaStreamWaitEvent(sA, evG1, 0);
    cudaStreamWaitEvent(sA, evCSR, 0);
    gather_agg_k<<<node_warp_blocks, 256, 0, sA>>>(xwb, csrc, off, rsd, din, b1, h1b, n, 1, 0);
    gemm_bf16_k<<<gemm_grid, 256, 2 * STAGE_BYTES, sA>>>(h1b, W2b, nullptr, nullptr, xwb, n, D, 0);
    gather_agg_k<<<node_warp_blocks, 256, 0, sA>>>(xwb, csrc, off, rsd, din, b2, zh, n, 0, 1);
    cudaEventRecord(evGCN, sA);

    // ---- main: target MLP branch ----
    zero2_k<<<1, 256>>>(musum, varsum, D);
    bnstat_k<<<100, 256>>>(tbuf, musum, varsum, n);
    bnapply_k<<<(nd + 255) / 256, 256>>>(tbuf, musum, varsum, gamma, beta, tb, n);
    gemm_bf16_k<<<gemm_grid, 256, 2 * STAGE_BYTES>>>(tb, Wt2b, bt2, nullptr, transb, n, D, 0);
    gemm_bf16_k<<<gemm_grid, 256, 2 * STAGE_BYTES>>>(transb, Wpb, bp, pbuf, nullptr, n, D, 0);
    norml1_k<<<(n * 32 + 255) / 256, 256>>>(pbuf, qh, n);
    cudaEventRecord(evQ, 0);
    zero2_k<<<(n + 255) / 256, 256>>>(s1, s2, n);
    zero_k<<<1, 32>>>(out, out_size);

    // ---- fork pos to sA ----
    cudaStreamWaitEvent(sA, evQ, 0);
    gather_pos_k<<<node_warp_blocks, 256, 0, sA>>>(zh, qh, csrc, off, pos, n);
    cudaEventRecord(evPos, sA);

    // ---- main: symmetric negsum ----
    cudaStreamWaitEvent(0, evGCN, 0);
    dim3 neg_grid(nTI, 24);
    negsym_k<<<neg_grid, 256, NEG_SMEM>>>(zh, qh, s1, s2, n, nTI);

    // ---- join + fused mneg + loss ----
    cudaStreamWaitEvent(0, evPos, 0);
    mneg_loss_k<<<node_warp_blocks, 256>>>(s1, s2, pos, csrc, off, out, n);
}

// round 15
// speedup vs baseline: 1.3458x; 1.0217x over previous
#include <cuda_runtime.h>
#include <cuda_bf16.h>
#include <stdint.h>
#include <math.h>

#define NMAX 10240
#define EMAX 340000
#define D 256
#define INMAX 512
#define TEMP_INV 2.0f
#define LAM 1e-3f
#define BN_EPS 1e-5f

// ------------------------------ scratch (BSS zero-initialized) ------------------------------
__device__ __align__(16) float g_t[NMAX * D];
__device__ __align__(16) float g_p[NMAX * D];
__device__ __align__(16) __nv_bfloat16 g_featb[NMAX * INMAX];
__device__ __align__(16) __nv_bfloat16 g_xwb[NMAX * D];
__device__ __align__(16) __nv_bfloat16 g_h1b[NMAX * D];
__device__ __align__(16) __nv_bfloat16 g_tb[NMAX * D];
__device__ __align__(16) __nv_bfloat16 g_zh[NMAX * D];
__device__ __align__(16) __nv_bfloat16 g_qh[NMAX * D];
__device__ __align__(16) __nv_bfloat16 g_Wcomb[INMAX * INMAX];  // rows 0-255 W1^T, 256-511 Wt1^T
__device__ __align__(16) __nv_bfloat16 g_W2b[D * D];
__device__ __align__(16) __nv_bfloat16 g_Wfb[D * D];            // folded (Wt2@Wp)^T bf16
__device__ float g_bfold[D];                                    // bt2@Wp + bp
__device__ float g_degout[NMAX];
__device__ float g_degin[NMAX];
__device__ float g_rsd[NMAX];
__device__ int   g_cnt[NMAX];
__device__ int   g_off[NMAX + 1];
__device__ int   g_cur[NMAX];
__device__ int   g_csrc[EMAX];
__device__ float g_musum[D];
__device__ float g_varsum[D];
__device__ float g_s1[NMAX];
__device__ float g_s2[NMAX];
__device__ float g_pos[NMAX];

// ------------------------------ small kernels ------------------------------
__global__ void zero2_k(float* a, float* b, int n) {
    int i = blockIdx.x * blockDim.x + threadIdx.x;
    if (i < n) { a[i] = 0.f; b[i] = 0.f; }
}
__global__ void zero3_k(float* a, float* b, int* c, int n) {
    int i = blockIdx.x * blockDim.x + threadIdx.x;
    if (i < n) { a[i] = 0.f; b[i] = 0.f; c[i] = 0; }
}
__global__ void zero_k(float* p, int n) {
    int i = blockIdx.x * blockDim.x + threadIdx.x;
    if (i < n) p[i] = 0.f;
}

__global__ void f2b_k(const float* __restrict__ x, __nv_bfloat16* __restrict__ y, int n) {
    int i = blockIdx.x * blockDim.x + threadIdx.x;
    if (i < n) y[i] = __float2bfloat16(x[i]);
}

// W1, Wt1 -> Wcomb halves; W2 -> W2b. All [K,N]->[N,K] bf16.
__global__ void wconvall_k(const float* W1, const float* Wt1, const float* W2,
                           __nv_bfloat16* W1c, __nv_bfloat16* Wt1c,
                           __nv_bfloat16* W2b) {
    int i = blockIdx.x * blockDim.x + threadIdx.x;
    const float* W; __nv_bfloat16* O; int K, li;
    if (i < 131072)        { W = W1;  O = W1c;  K = 512; li = i; }
    else if (i < 262144)   { W = Wt1; O = Wt1c; K = 512; li = i - 131072; }
    else if (i < 327680)   { W = W2;  O = W2b;  K = 256; li = i - 262144; }
    else return;
    int k = li >> 8, n = li & 255;
    O[n * K + k] = __float2bfloat16(W[(size_t)k * 256 + n]);
}

// fold: Wfb[j,k] = sum_m Wt2[k,m]*Wp[m,j] (bf16); bfold[j] = sum_m bt2[m]*Wp[m,j] + bp[j]
__global__ void wfold_k(const float* __restrict__ Wt2, const float* __restrict__ Wp,
                        const float* __restrict__ bt2, const float* __restrict__ bp,
                        __nv_bfloat16* __restrict__ Wfb, float* __restrict__ bfold) {
    int k = blockIdx.x;
    int j = threadIdx.x;
    float s = 0.f;
    for (int m = 0; m < D; m++)
        s += Wt2[k * D + m] * Wp[(size_t)m * D + j];
    Wfb[j * D + k] = __float2bfloat16(s);
    if (k == 0) {
        float b = bp[j];
        for (int m = 0; m < D; m++) b += bt2[m] * Wp[(size_t)m * D + j];
        bfold[j] = b;
    }
}

__global__ void degree_k(const int* __restrict__ src, const int* __restrict__ dst,
                         float* dout, float* din, int* cnt, int e) {
    int i = blockIdx.x * blockDim.x + threadIdx.x;
    if (i < e) {
        atomicAdd(&dout[src[i]], 1.f);
        atomicAdd(&din[dst[i]], 1.f);
        atomicAdd(&cnt[dst[i]], 1);
    }
}

__global__ void rsdcur_k(const float* __restrict__ dout, float* rsd, int* cur, int n) {
    int i = blockIdx.x * blockDim.x + threadIdx.x;
    if (i < n) { rsd[i] = rsqrtf(dout[i]); cur[i] = 0; }
}

__global__ void scan_k(const int* __restrict__ cnt, int* off, int n) {
    __shared__ int ts[1024];
    int t = threadIdx.x;
    int L = (n + 1023) >> 10;
    int b = t * L, eidx = min(b + L, n);
    int s = 0;
    for (int i = b; i < eidx; i++) s += cnt[i];
    ts[t] = s;
    __syncthreads();
    for (int d2 = 1; d2 < 1024; d2 <<= 1) {
        int v = (t >= d2) ? ts[t - d2] : 0;
        __syncthreads();
        ts[t] += v;
        __syncthreads();
    }
    int base = (t == 0) ? 0 : ts[t - 1];
    for (int i = b; i < eidx; i++) { off[i] = base; base += cnt[i]; }
    if (t == 1023) off[n] = ts[1023];
}

__global__ void fillcsr_k(const int* __restrict__ src, const int* __restrict__ dst,
                          const int* __restrict__ off, int* cur, int* csrc, int e) {
    int i = blockIdx.x * blockDim.x + threadIdx.x;
    if (i < e) {
        int d = dst[i];
        int p = off[d] + atomicAdd(&cur[d], 1);
        csrc[p] = src[i];
    }
}

__global__ void gather_agg_k(const __nv_bfloat16* __restrict__ xw,
                             const int* __restrict__ csrc, const int* __restrict__ off,
                             const float* __restrict__ rsd, const float* __restrict__ din,
                             const float* __restrict__ bias,
                             __nv_bfloat16* outh, int n, int relu, int norm) {
    int d = (blockIdx.x * blockDim.x + threadIdx.x) >> 5;
    int lane = threadIdx.x & 31;
    if (d >= n) return;
    float acc[8] = {};
    int p0 = off[d], p1 = off[d + 1];
    int p = p0;
    for (; p + 8 <= p1; p += 8) {
        int si[8];
#pragma unroll
        for (int u = 0; u < 8; u++) si[u] = __ldg(csrc + p + u);
        uint4 v[8];
#pragma unroll
        for (int u = 0; u < 8; u++) v[u] = *((const uint4*)(xw + (size_t)si[u] * D) + lane);
        float w[8];
#pragma unroll
        for (int u = 0; u < 8; u++) w[u] = rsd[si[u]];
#pragma unroll
        for (int u = 0; u < 8; u++) {
            const __nv_bfloat16* hv = (const __nv_bfloat16*)&v[u];
#pragma unroll
            for (int k = 0; k < 8; k++) acc[k] += __bfloat162float(hv[k]) * w[u];
        }
    }
    for (; p < p1; p++) {
        int s = __ldg(csrc + p);
        float w = rsd[s];
        uint4 vv = *((const uint4*)(xw + (size_t)s * D) + lane);
        const __nv_bfloat16* hv = (const __nv_bfloat16*)&vv;
#pragma unroll
        for (int k = 0; k < 8; k++) acc[k] += __bfloat162float(hv[k]) * w;
    }
    float sc = rsqrtf(din[d]);
    int col = lane * 8;
    float o[8];
#pragma unroll
    for (int k = 0; k < 8; k++) {
        float v = acc[k] * sc + bias[col + k];
        o[k] = relu ? fmaxf(v, 0.f) : v;
    }
    if (norm) {
        float ss = 0.f;
#pragma unroll
        for (int k = 0; k < 8; k++) ss += o[k] * o[k];
#pragma unroll
        for (int os = 16; os > 0; os >>= 1) ss += __shfl_xor_sync(0xffffffffu, ss, os);
        float inv = 1.f / fmaxf(sqrtf(ss), 1e-12f);
#pragma unroll
        for (int k = 0; k < 8; k++) o[k] *= inv;
    }
    __nv_bfloat16 hb[8];
#pragma unroll
    for (int k = 0; k < 8; k++) hb[k] = __float2bfloat16(o[k]);
    *(uint4*)(outh + (size_t)d * D + col) = *(uint4*)hb;
}

__global__ void bnstat_k(const float* __restrict__ t, float* musum, float* varsum, int M) {
    int col = threadIdx.x;
    int rpb = (M + gridDim.x - 1) / gridDim.x;
    int r0 = blockIdx.x * rpb;
    int r1 = min(r0 + rpb, M);
    float s = 0.f, s2 = 0.f;
    for (int r = r0; r < r1; r++) {
        float v = t[(size_t)r * D + col];
        s += v; s2 += v * v;
    }
    atomicAdd(&musum[col], s);
    atomicAdd(&varsum[col], s2);
}

__global__ void bnapply_k(const float* __restrict__ t, const float* __restrict__ musum,
                          const float* __restrict__ varsum,
                          const float* __restrict__ gamma, const float* __restrict__ beta,
                          __nv_bfloat16* th, int M) {
    int i = blockIdx.x * blockDim.x + threadIdx.x;
    if (i < M * D) {
        int c = i & (D - 1);
        float mu = musum[c] / M;
        float var = varsum[c] / M - mu * mu;
        float v = (t[i] - mu) * rsqrtf(var + BN_EPS) * gamma[c] + beta[c];
        th[i] = __float2bfloat16(fmaxf(v, 0.f));
    }
}

__global__ void norml1_k(const float* __restrict__ x, __nv_bfloat16* __restrict__ zh, int M) {
    int row = (blockIdx.x * blockDim.x + threadIdx.x) >> 5;
    int lane = threadIdx.x & 31;
    if (row >= M) return;
    const float* xr = x + (size_t)row * D;
    float s = 0.f;
#pragma unroll
    for (int c = 0; c < D / 32; c++) {
        float v = xr[lane + 32 * c];
        s += v * v;
    }
#pragma unroll
    for (int o = 16; o > 0; o >>= 1) s += __shfl_xor_sync(0xffffffffu, s, o);
    float inv = 1.f / fmaxf(sqrtf(s), 1e-12f);
    __nv_bfloat16* hr = zh + (size_t)row * D;
#pragma unroll
    for (int c = 0; c < D / 32; c++) {
        int f = lane + 32 * c;
        hr[f] = __float2bfloat16(xr[f] * inv);
    }
}

__global__ void gather_pos_k(const __nv_bfloat16* __restrict__ zh,
                             const __nv_bfloat16* __restrict__ qh,
                             const int* __restrict__ csrc, const int* __restrict__ off,
                             float* pos, int n) {
    int d = (blockIdx.x * blockDim.x + threadIdx.x) >> 5;
    int lane = threadIdx.x & 31;
    if (d >= n) return;
    uint4 qv = *((const uint4*)(qh + (size_t)d * D) + lane);
    const __nv_bfloat16* qe = (const __nv_bfloat16*)&qv;
    float qf[8];
#pragma unroll
    for (int k = 0; k < 8; k++) qf[k] = __bfloat162float(qe[k]);
    float sz[8] = {};
    int p0 = off[d], p1 = off[d + 1];
    int p = p0;
    for (; p + 8 <= p1; p += 8) {
        int si[8];
#pragma unroll
        for (int u = 0; u < 8; u++) si[u] = __ldg(csrc + p + u);
        uint4 v[8];
#pragma unroll
        for (int u = 0; u < 8; u++) v[u] = *((const uint4*)(zh + (size_t)si[u] * D) + lane);
#pragma unroll
        for (int u = 0; u < 8; u++) {
            const __nv_bfloat16* hv = (const __nv_bfloat16*)&v[u];
#pragma unroll
            for (int k = 0; k < 8; k++) sz[k] += __bfloat162float(hv[k]);
        }
    }
    for (; p < p1; p++) {
        int s = __ldg(csrc + p);
        uint4 vv = *((const uint4*)(zh + (size_t)s * D) + lane);
        const __nv_bfloat16* hv = (const __nv_bfloat16*)&vv;
#pragma unroll
        for (int k = 0; k < 8; k++) sz[k] += __bfloat162float(hv[k]);
    }
    float dot = 0.f;
#pragma unroll
    for (int k = 0; k < 8; k++) dot += sz[k] * qf[k];
#pragma unroll
    for (int o = 16; o > 0; o >>= 1) dot += __shfl_xor_sync(0xffffffffu, dot, o);
    if (lane == 0) pos[d] = dot * TEMP_INV;
}

__global__ void mneg_loss_k(const float* __restrict__ s1, const float* __restrict__ s2,
                            const float* __restrict__ pos,
                            const int* __restrict__ csrc, const int* __restrict__ off,
                            float* out, int n) {
    __shared__ float ws[8];
    int tid = threadIdx.x;
    int lane = tid & 31, warp = tid >> 5;
    int d = (blockIdx.x * blockDim.x + tid) >> 5;
    float contrib = 0.f;
    if (d < n) {
        float base = s1[d];
        float acc = 0.f;
        int p0 = off[d], p1 = off[d + 1];
        for (int p = p0 + lane; p < p1; p += 32)
            acc += __logf(base + LAM * s2[__ldg(csrc + p)]);
#pragma unroll
        for (int o = 16; o > 0; o >>= 1) acc += __shfl_xor_sync(0xffffffffu, acc, o);
        if (lane == 0) contrib = (acc - pos[d]) / (float)(p1 - p0);
    }
    if (lane == 0) ws[warp] = contrib;
    __syncthreads();
    if (tid == 0) {
        float t = 0.f;
#pragma unroll
        for (int w = 0; w < 8; w++) t += ws[w];
        atomicAdd(out, t / n);
    }
}

// ---------------- mma helpers ----------------
__device__ __forceinline__ void ldsm4(uint32_t addr, uint32_t& r0, uint32_t& r1,
                                      uint32_t& r2, uint32_t& r3) {
    asm volatile("ldmatrix.sync.aligned.m8n8.x4.shared.b16 {%0,%1,%2,%3}, [%4];"
                 : "=r"(r0), "=r"(r1), "=r"(r2), "=r"(r3) : "r"(addr));
}
__device__ __forceinline__ void mma16816(float* c, const uint32_t* a,
                                         uint32_t b0, uint32_t b1) {
    asm volatile(
        "mma.sync.aligned.m16n8k16.row.col.f32.bf16.bf16.f32 "
        "{%0,%1,%2,%3}, {%4,%5,%6,%7}, {%8,%9}, {%0,%1,%2,%3};"
        : "+f"(c[0]), "+f"(c[1]), "+f"(c[2]), "+f"(c[3])
        : "r"(a[0]), "r"(a[1]), "r"(a[2]), "r"(a[3]), "r"(b0), "r"(b1));
}
__device__ __forceinline__ void cp16(uint32_t saddr, const void* g) {
    asm volatile("cp.async.cg.shared.global [%0], [%1], 16;"
                 :: "r"(saddr), "l"(g) : "memory");
}
__device__ __forceinline__ void loadB64(uint32_t sdst, const __nv_bfloat16* Bg,
                                        int k0, int ldb, int tid) {
#pragma unroll
    for (int t = 0; t < 4; t++) {
        int c = tid + t * 256;
        int row = c >> 3, ch = c & 7;
        uint32_t off = (uint32_t)(row * 128 + ((ch ^ (row & 7)) << 4));
        cp16(sdst + off, Bg + (size_t)row * ldb + k0 + ch * 8);
    }
    asm volatile("cp.async.commit_group;" ::: "memory");
}

#define STAGE_BYTES 32768

#define GEMM_MAINLOOP(A_, B_, K_)                                                     \
    int KT = (K_) >> 6;                                                               \
    loadB64(sbase, (A_), 0, (K_), tid);                                               \
    loadB64(sbase + 16384, (B_), 0, (K_), tid);                                       \
    for (int kt = 0; kt < KT; kt++) {                                                 \
        asm volatile("cp.async.wait_group 0;" ::: "memory");                          \
        __syncthreads();                                                              \
        if (kt + 1 < KT) {                                                            \
            uint32_t sa = sbase + ((kt + 1) & 1) * STAGE_BYTES;                       \
            loadB64(sa, (A_), (kt + 1) * 64, (K_), tid);                              \
            loadB64(sa + 16384, (B_), (kt + 1) * 64, (K_), tid);                      \
        }                                                                             \
        uint32_t sAu = sbase + (kt & 1) * STAGE_BYTES;                                \
        uint32_t sBu = sAu + 16384;                                                   \
        _Pragma("unroll")                                                             \
        for (int ks = 0; ks < 4; ks++) {                                              \
            uint32_t afr[2][4];                                                       \
            _Pragma("unroll")                                                         \
            for (int mt = 0; mt < 2; mt++) {                                          \
                int row = wi * 32 + mt * 16 + a_row;                                  \
                int ch = ks * 2 + a_chsel;                                            \
                uint32_t addr = sAu + (uint32_t)(row * 128 + ((ch ^ (row & 7)) << 4));\
                ldsm4(addr, afr[mt][0], afr[mt][1], afr[mt][2], afr[mt][3]);          \
            }                                                                         \
            _Pragma("unroll")                                                         \
            for (int pp = 0; pp < 4; pp++) {                                          \
                int nrow = wj * 64 + pp * 16 + b_row;                                 \
                int ch = ks * 2 + b_chsel;                                            \
                uint32_t addr = sBu + (uint32_t)(nrow * 128 + ((ch ^ (nrow & 7)) << 4));\
                uint32_t bf0, bf1, bf2, bf3;                                          \
                ldsm4(addr, bf0, bf1, bf2, bf3);                                      \
                _Pragma("unroll")                                                     \
                for (int mt = 0; mt < 2; mt++) {                                      \
                    mma16816(acc[mt][2 * pp], afr[mt], bf0, bf1);                     \
                    mma16816(acc[mt][2 * pp + 1], afr[mt], bf2, bf3);                 \
                }                                                                     \
            }                                                                         \
        }                                                                             \
        __syncthreads();                                                              \
    }

// ---------------- bf16 tensor GEMM: C = A[Mpad,K] @ Wt[256,K]^T ----------------
__global__ __launch_bounds__(256, 2) void gemm_bf16_k(
    const __nv_bfloat16* __restrict__ A, const __nv_bfloat16* __restrict__ Wt,
    const float* __restrict__ bias, float* __restrict__ Cf,
    __nv_bfloat16* __restrict__ Ch, int M, int K, int relu) {
    extern __shared__ char dsm[];
    uint32_t sbase = (uint32_t)__cvta_generic_to_shared(dsm);
    int tid = threadIdx.x;
    int lane = tid & 31, warp = tid >> 5;
    int wi = warp >> 1, wj = warp & 1;
    int i0 = blockIdx.x * 128, j0 = blockIdx.y * 128;

    int a_row = (lane & 15);
    int a_chsel = (lane >> 4);
    int b_row = (lane & 7) + ((lane >> 4) & 1) * 8;
    int b_chsel = ((lane >> 3) & 1);

    const __nv_bfloat16* Ag = A + (size_t)i0 * K;
    const __nv_bfloat16* Bg = Wt + (size_t)j0 * K;

    float acc[2][8][4];
#pragma unroll
    for (int x = 0; x < 2; x++)
#pragma unroll
        for (int y = 0; y < 8; y++)
#pragma unroll
            for (int v = 0; v < 4; v++) acc[x][y][v] = 0.f;

    GEMM_MAINLOOP(Ag, Bg, K)

#pragma unroll
    for (int mt = 0; mt < 2; mt++) {
        int r0 = i0 + wi * 32 + mt * 16 + (lane >> 2);
#pragma unroll
        for (int nt = 0; nt < 8; nt++) {
            int col = j0 + wj * 64 + nt * 8 + (lane & 3) * 2;
            float b0 = bias ? bias[col] : 0.f;
            float b1 = bias ? bias[col + 1] : 0.f;
            float v0 = acc[mt][nt][0] + b0, v1 = acc[mt][nt][1] + b1;
            float v2 = acc[mt][nt][2] + b0, v3 = acc[mt][nt][3] + b1;
            if (relu) {
                v0 = fmaxf(v0, 0.f); v1 = fmaxf(v1, 0.f);
                v2 = fmaxf(v2, 0.f); v3 = fmaxf(v3, 0.f);
            }
            if (r0 < M) {
                if (Cf) { Cf[(size_t)r0 * D + col] = v0; Cf[(size_t)r0 * D + col + 1] = v1; }
                if (Ch) {
                    Ch[(size_t)r0 * D + col] = __float2bfloat16(v0);
                    Ch[(size_t)r0 * D + col + 1] = __float2bfloat16(v1);
                }
            }
            int r1 = r0 + 8;
            if (r1 < M) {
                if (Cf) { Cf[(size_t)r1 * D + col] = v2; Cf[(size_t)r1 * D + col + 1] = v3; }
                if (Ch) {
                    Ch[(size_t)r1 * D + col] = __float2bfloat16(v2);
                    Ch[(size_t)r1 * D + col + 1] = __float2bfloat16(v3);
                }
            }
        }
    }
}

// ---------------- dual-output gemm: featb @ Wcomb[512,512]^T ----------------
__global__ __launch_bounds__(256, 2) void gemm_dual_k(
    const __nv_bfloat16* __restrict__ A, const __nv_bfloat16* __restrict__ Wc,
    const float* __restrict__ bt1, __nv_bfloat16* __restrict__ Xh,
    float* __restrict__ Tf, int M, int K) {
    extern __shared__ char dsm[];
    uint32_t sbase = (uint32_t)__cvta_generic_to_shared(dsm);
    int tid = threadIdx.x;
    int lane = tid & 31, warp = tid >> 5;
    int wi = warp >> 1, wj = warp & 1;
    int i0 = blockIdx.x * 128, j0 = blockIdx.y * 128;

    int a_row = (lane & 15);
    int a_chsel = (lane >> 4);
    int b_row = (lane & 7) + ((lane >> 4) & 1) * 8;
    int b_chsel = ((lane >> 3) & 1);

    const __nv_bfloat16* Ag = A + (size_t)i0 * K;
    const __nv_bfloat16* Bg = Wc + (size_t)j0 * K;

    float acc[2][8][4];
#pragma unroll
    for (int x = 0; x < 2; x++)
#pragma unroll
        for (int y = 0; y < 8; y++)
#pragma unroll
            for (int v = 0; v < 4; v++) acc[x][y][v] = 0.f;

    GEMM_MAINLOOP(Ag, Bg, K)

    int isT = (j0 >= 256);
#pragma unroll
    for (int mt = 0; mt < 2; mt++) {
        int r0 = i0 + wi * 32 + mt * 16 + (lane >> 2);
#pragma unroll
        for (int nt = 0; nt < 8; nt++) {
            int col = j0 + wj * 64 + nt * 8 + (lane & 3) * 2;
            if (isT) {
                int c2 = col - 256;
                float b0 = bt1[c2], b1 = bt1[c2 + 1];
                if (r0 < M) {
                    Tf[(size_t)r0 * D + c2] = acc[mt][nt][0] + b0;
                    Tf[(size_t)r0 * D + c2 + 1] = acc[mt][nt][1] + b1;
                }
                int r1 = r0 + 8;
                if (r1 < M) {
                    Tf[(size_t)r1 * D + c2] = acc[mt][nt][2] + b0;
                    Tf[(size_t)r1 * D + c2 + 1] = acc[mt][nt][3] + b1;
                }
            } else {
                if (r0 < M) {
                    Xh[(size_t)r0 * D + col] = __float2bfloat16(acc[mt][nt][0]);
                    Xh[(size_t)r0 * D + col + 1] = __float2bfloat16(acc[mt][nt][1]);
                }
                int r1 = r0 + 8;
                if (r1 < M) {
                    Xh[(size_t)r1 * D + col] = __float2bfloat16(acc[mt][nt][2]);
                    Xh[(size_t)r1 * D + col + 1] = __float2bfloat16(acc[mt][nt][3]);
                }
            }
        }
    }
}

// ---------------- symmetric fused dual negsum ----------------
#define NEG_SMEM (98304 + 512)

__global__ __launch_bounds__(256, 2) void negsym_k(
    const __nv_bfloat16* __restrict__ Z, const __nv_bfloat16* __restrict__ Q,
    float* __restrict__ s1, float* __restrict__ s2, int n, int nTI) {
    extern __shared__ char dsm[];
    uint32_t aBase = (uint32_t)__cvta_generic_to_shared(dsm);        // 64 KB
    uint32_t bBase = aBase + 65536;                                   // 2 x 16 KB
    float* colsm = (float*)(dsm + 98304);                             // 128 floats
    int tid = threadIdx.x;
    int lane = tid & 31, warp = tid >> 5;
    int wi = warp >> 1, wj = warp & 1;
    int it = blockIdx.x;
    int i0 = it * 128;
    int gy = gridDim.y, by = blockIdx.y;

    int a_row = (lane & 15);
    int a_chsel = (lane >> 4);
    int b_row = (lane & 7) + ((lane >> 4) & 1) * 8;
    int b_chsel = ((lane >> 3) & 1);

#pragma unroll
    for (int t = 0; t < 16; t++) {
        int c = tid + t * 256;
        int blk = c >> 10, idx = c & 1023;
        int row = idx >> 3, ch = idx & 7;
        uint32_t off = (uint32_t)(blk * 16384 + row * 128 + ((ch ^ (row & 7)) << 4));
        cp16(aBase + off, Z + (size_t)(i0 + row) * D + blk * 64 + ch * 8);
    }
    asm volatile("cp.async.commit_group;" ::: "memory");

    float rs[2][2][2];
#pragma unroll
    for (int a = 0; a < 2; a++)
#pragma unroll
        for (int b = 0; b < 2; b++)
#pragma unroll
            for (int c = 0; c < 2; c++) rs[a][b][c] = 0.f;

    int rbase = i0 + wi * 32 + (lane >> 2);
    float rv[2][2];
#pragma unroll
    for (int mt = 0; mt < 2; mt++) {
        rv[mt][0] = (rbase + mt * 16 < n) ? 1.f : 0.f;
        rv[mt][1] = (rbase + mt * 16 + 8 < n) ? 1.f : 0.f;
    }

#pragma unroll 1
    for (int sel = 0; sel < 2; sel++) {
        int jt0 = sel ? by : (it + by);
#pragma unroll 1
        for (int jt = jt0; jt < nTI; jt += gy) {
            int j0 = jt * 128;
            const __nv_bfloat16* Bg = (sel ? Q : Z) + (size_t)j0 * D;
            loadB64(bBase, Bg, 0, D, tid);
            float acc[2][8][4];
#pragma unroll
            for (int x = 0; x < 2; x++)
#pragma unroll
                for (int y = 0; y < 8; y++)
#pragma unroll
                    for (int v = 0; v < 4; v++) acc[x][y][v] = 0.f;

#pragma unroll
            for (int kt = 0; kt < 4; kt++) {
                asm volatile("cp.async.wait_group 0;" ::: "memory");
                __syncthreads();
                if (kt < 3) loadB64(bBase + ((kt + 1) & 1) * 16384, Bg, (kt + 1) * 64, D, tid);
                uint32_t sAu = aBase + kt * 16384;
                uint32_t sBu = bBase + (kt & 1) * 16384;
#pragma unroll
                for (int ks = 0; ks < 4; ks++) {
                    uint32_t afr[2][4];
#pragma unroll
                    for (int mt = 0; mt < 2; mt++) {
                        int row = wi * 32 + mt * 16 + a_row;
                        int ch = ks * 2 + a_chsel;
                        uint32_t addr = sAu + (uint32_t)(row * 128 + ((ch ^ (row & 7)) << 4));
                        ldsm4(addr, afr[mt][0], afr[mt][1], afr[mt][2], afr[mt][3]);
                    }
#pragma unroll
                    for (int p = 0; p < 4; p++) {
                        int nrow = wj * 64 + p * 16 + b_row;
                        int ch = ks * 2 + b_chsel;
                        uint32_t addr = sBu + (uint32_t)(nrow * 128 + ((ch ^ (nrow & 7)) << 4));
                        uint32_t bf0, bf1, bf2, bf3;
                        ldsm4(addr, bf0, bf1, bf2, bf3);
#pragma unroll
                        for (int mt = 0; mt < 2; mt++) {
                            mma16816(acc[mt][2 * p], afr[mt], bf0, bf1);
                            mma16816(acc[mt][2 * p + 1], afr[mt], bf2, bf3);
                        }
                    }
                }
                __syncthreads();
            }
            int doCol = (sel == 0) && (jt != it);
            if (doCol) {
                if (tid < 128) colsm[tid] = 0.f;
                __syncthreads();
            }
            float cs[8][2];
#pragma unroll
            for (int mt = 0; mt < 2; mt++) {
#pragma unroll
                for (int nt = 0; nt < 8; nt++) {
                    int j = j0 + wj * 64 + nt * 8 + (lane & 3) * 2;
                    float e0 = (j < n) ? __expf(acc[mt][nt][0] * TEMP_INV) : 0.f;
                    float e1 = (j + 1 < n) ? __expf(acc[mt][nt][1] * TEMP_INV) : 0.f;
                    float e2 = (j < n) ? __expf(acc[mt][nt][2] * TEMP_INV) : 0.f;
                    float e3 = (j + 1 < n) ? __expf(acc[mt][nt][3] * TEMP_INV) : 0.f;
                    rs[sel][mt][0] += e0 + e1;
                    rs[sel][mt][1] += e2 + e3;
                    if (doCol) {
                        float c0 = e0 * rv[mt][0] + e2 * rv[mt][1];
                        float c1 = e1 * rv[mt][0] + e3 * rv[mt][1];
                        if (mt == 0) { cs[nt][0] = c0; cs[nt][1] = c1; }
                        else { cs[nt][0] += c0; cs[nt][1] += c1; }
                    }
                }
            }
            if (doCol) {
#pragma unroll
                for (int nt = 0; nt < 8; nt++) {
#pragma unroll
                    for (int h = 0; h < 2; h++) {
                        float v = cs[nt][h];
                        v += __shfl_xor_sync(0xffffffffu, v, 4);
                        v += __shfl_xor_sync(0xffffffffu, v, 8);
                        v += __shfl_xor_sync(0xffffffffu, v, 16);
                        cs[nt][h] = v;
                    }
                }
                if (lane < 4) {
#pragma unroll
                    for (int nt = 0; nt < 8; nt++) {
                        int cc = wj * 64 + nt * 8 + lane * 2;
                        atomicAdd(&colsm[cc], cs[nt][0]);
                        atomicAdd(&colsm[cc + 1], cs[nt][1]);
                    }
                }
                __syncthreads();
                if (tid < 128) {
                    int j = j0 + tid;
                    if (j < n) atomicAdd(&s1[j], colsm[tid]);
                }
                __syncthreads();
            }
        }
    }
#pragma unroll
    for (int sel = 0; sel < 2; sel++) {
        float* out = sel ? s2 : s1;
#pragma unroll
        for (int mt = 0; mt < 2; mt++) {
#pragma unroll
            for (int h = 0; h < 2; h++) {
                float v = rs[sel][mt][h];
                v += __shfl_xor_sync(0xffffffffu, v, 1);
                v += __shfl_xor_sync(0xffffffffu, v, 2);
                if ((lane & 3) == 0) {
                    int i = i0 + wi * 32 + mt * 16 + h * 8 + (lane >> 2);
                    if (i < n) atomicAdd(&out[i], v);
                }
            }
        }
    }
}

// ------------------------------ launcher ------------------------------
static float* symf(const void* s) { void* p = nullptr; cudaGetSymbolAddress(&p, s); return (float*)p; }
static int* symi(const void* s) { void* p = nullptr; cudaGetSymbolAddress(&p, s); return (int*)p; }
static __nv_bfloat16* symh(const void* s) { void* p = nullptr; cudaGetSymbolAddress(&p, s); return (__nv_bfloat16*)p; }

extern "C" void kernel_launch(void* const* d_in, const int* in_sizes, int n_in,
                              void* d_out, int out_size) {
    const float* feat  = (const float*)d_in[0];
    const float* W1    = (const float*)d_in[1];
    const float* b1    = (const float*)d_in[2];
    const float* W2    = (const float*)d_in[3];
    const float* b2    = (const float*)d_in[4];
    const float* Wt1   = (const float*)d_in[5];
    const float* bt1   = (const float*)d_in[6];
    const float* gamma = (const float*)d_in[7];
    const float* beta  = (const float*)d_in[8];
    const float* Wt2   = (const float*)d_in[9];
    const float* bt2   = (const float*)d_in[10];
    const float* Wp    = (const float*)d_in[11];
    const float* bp    = (const float*)d_in[12];
    const int*   src   = (const int*)d_in[13];
    const int*   dst   = (const int*)d_in[14];

    const int IN = 512;
    int n = in_sizes[0] / IN;
    int e = in_sizes[13];
    int nTI = (n + 127) / 128;

    float* tbuf = symf(g_t);
    float* pbuf = symf(g_p);
    __nv_bfloat16* featb = symh(g_featb);
    __nv_bfloat16* xwb = symh(g_xwb);
    __nv_bfloat16* h1b = symh(g_h1b);
    __nv_bfloat16* tb = symh(g_tb);
    __nv_bfloat16* zh = symh(g_zh);
    __nv_bfloat16* qh = symh(g_qh);
    __nv_bfloat16* Wcomb = symh(g_Wcomb);
    __nv_bfloat16* W2b = symh(g_W2b);
    __nv_bfloat16* Wfb = symh(g_Wfb);
    float* bfold = symf(g_bfold);
    float* dout = symf(g_degout);
    float* din  = symf(g_degin);
    float* rsd  = symf(g_rsd);
    int* cnt = symi(g_cnt);
    int* off = symi(g_off);
    int* cur = symi(g_cur);
    int* csrc = symi(g_csrc);
    float* musum = symf(g_musum);
    float* varsum = symf(g_varsum);
    float* s1 = symf(g_s1);
    float* s2 = symf(g_s2);
    float* pos = symf(g_pos);
    float* out = (float*)d_out;

    int nd = n * D;
    dim3 gemm_grid(nTI, 2);
    dim3 dual_grid(nTI, 4);
    int node_warp_blocks = (n * 32 + 255) / 256;

    static cudaStream_t sA = nullptr, sB = nullptr;
    static cudaEvent_t evStart, evCSR, evFold, evG1, evGCN, evQ, evPos;
    if (sA == nullptr) {
        cudaStreamCreateWithFlags(&sA, cudaStreamNonBlocking);
        cudaStreamCreateWithFlags(&sB, cudaStreamNonBlocking);
        cudaEventCreateWithFlags(&evStart, cudaEventDisableTiming);
        cudaEventCreateWithFlags(&evCSR, cudaEventDisableTiming);
        cudaEventCreateWithFlags(&evFold, cudaEventDisableTiming);
        cudaEventCreateWithFlags(&evG1, cudaEventDisableTiming);
        cudaEventCreateWithFlags(&evGCN, cudaEventDisableTiming);
        cudaEventCreateWithFlags(&evQ, cudaEventDisableTiming);
        cudaEventCreateWithFlags(&evPos, cudaEventDisableTiming);
        cudaFuncSetAttribute(gemm_bf16_k, cudaFuncAttributeMaxDynamicSharedMemorySize, 2 * STAGE_BYTES);
        cudaFuncSetAttribute(gemm_dual_k, cudaFuncAttributeMaxDynamicSharedMemorySize, 2 * STAGE_BYTES);
        cudaFuncSetAttribute(negsym_k, cudaFuncAttributeMaxDynamicSharedMemorySize, NEG_SMEM);
    }

    // ---- fork CSR chain + weight fold to sB ----
    cudaEventRecord(evStart, 0);
    cudaStreamWaitEvent(sB, evStart, 0);
    zero3_k<<<(n + 255) / 256, 256, 0, sB>>>(dout, din, cnt, n);
    degree_k<<<(e + 255) / 256, 256, 0, sB>>>(src, dst, dout, din, cnt, e);
    rsdcur_k<<<(n + 255) / 256, 256, 0, sB>>>(dout, rsd, cur, n);
    scan_k<<<1, 1024, 0, sB>>>(cnt, off, n);
    fillcsr_k<<<(e + 255) / 256, 256, 0, sB>>>(src, dst, off, cur, csrc, e);
    cudaEventRecord(evCSR, sB);
    wfold_k<<<D, D, 0, sB>>>(Wt2, Wp, bt2, bp, Wfb, bfold);
    cudaEventRecord(evFold, sB);

    // ---- main: conversions + dual first-layer gemm ----
    f2b_k<<<(n * IN + 255) / 256, 256>>>(feat, featb, n * IN);
    wconvall_k<<<(327680 + 255) / 256, 256>>>(W1, Wt1, W2, Wcomb, Wcomb + 256 * 512, W2b);
    gemm_dual_k<<<dual_grid, 256, 2 * STAGE_BYTES>>>(featb, Wcomb, bt1, xwb, tbuf, n, IN);
    cudaEventRecord(evG1, 0);

    // ---- fork GCN branch to sA ----
    cudaStreamWaitEvent(sA, evG1, 0);
    cudaStreamWaitEvent(sA, evCSR, 0);
    gather_agg_k<<<node_warp_blocks, 256, 0, sA>>>(xwb, csrc, off, rsd, din, b1, h1b, n, 1, 0);
    gemm_bf16_k<<<gemm_grid, 256, 2 * STAGE_BYTES, sA>>>(h1b, W2b, nullptr, nullptr, xwb, n, D, 0);
    gather_agg_k<<<node_warp_blocks, 256, 0, sA>>>(xwb, csrc, off, rsd, din, b2, zh, n, 0, 1);
    cudaEventRecord(evGCN, sA);

    // ---- main: target MLP branch (folded) ----
    zero2_k<<<1, 256>>>(musum, varsum, D);
    bnstat_k<<<100, 256>>>(tbuf, musum, varsum, n);
    bnapply_k<<<(nd + 255) / 256, 256>>>(tbuf, musum, varsum, gamma, beta, tb, n);
    cudaStreamWaitEvent(0, evFold, 0);
    gemm_bf16_k<<<gemm_grid, 256, 2 * STAGE_BYTES>>>(tb, Wfb, bfold, pbuf, nullptr, n, D, 0);
    norml1_k<<<(n * 32 + 255) / 256, 256>>>(pbuf, qh, n);
    cudaEventRecord(evQ, 0);
    zero2_k<<<(n + 255) / 256, 256>>>(s1, s2, n);
    zero_k<<<1, 32>>>(out, out_size);

    // ---- fork pos to sA ----
    cudaStreamWaitEvent(sA, evQ, 0);
    gather_pos_k<<<node_warp_blocks, 256, 0, sA>>>(zh, qh, csrc, off, pos, n);
    cudaEventRecord(evPos, sA);

    // ---- main: symmetric negsum ----
    cudaStreamWaitEvent(0, evGCN, 0);
    dim3 neg_grid(nTI, 24);
    negsym_k<<<neg_grid, 256, NEG_SMEM>>>(zh, qh, s1, s2, n, nTI);

    // ---- join + fused mneg + loss ----
    cudaStreamWaitEvent(0, evPos, 0);
    mneg_loss_k<<<node_warp_blocks, 256>>>(s1, s2, pos, csrc, off, out, n);
}